// round 8
// baseline (speedup 1.0000x reference)
#include <cuda_runtime.h>
#include <cstddef>

// ---------------------------------------------------------------------------
// Problem constants
// ---------------------------------------------------------------------------
constexpr int B_  = 2;
constexpr int C_  = 64;
constexpr int C4_ = 256;
constexpr int H_  = 64;
constexpr int W_  = 96;
constexpr int HW_ = H_ * W_;
constexpr int NSB = 2 * B_;   // side * batch slots

typedef unsigned long long ull;

// Scratch (device globals: no allocations allowed). Layout [side*B+b][C4][HW]
__device__ float g_t1[(size_t)NSB * C4_ * HW_];
__device__ float g_t2[(size_t)NSB * C4_ * HW_];
__device__ float g_Q [(size_t)B_ * C_  * HW_];
__device__ float g_K [(size_t)B_ * C_  * HW_];

// ---------------------------------------------------------------------------
// f32x2 helpers (sm_100+ packed fp32 — exact, two independent IEEE FMAs)
// ---------------------------------------------------------------------------
__device__ __forceinline__ ull pk2(float a, float b) {
    ull r;
    asm("mov.b64 %0, {%1, %2};" : "=l"(r)
        : "r"(__float_as_uint(a)), "r"(__float_as_uint(b)));
    return r;
}
__device__ __forceinline__ void fma2(ull& d, ull a, ull b) {
    asm("fma.rn.f32x2 %0, %1, %2, %0;" : "+l"(d) : "l"(a), "l"(b));
}
__device__ __forceinline__ void unpk2(ull v, float& lo, float& hi) {
    unsigned l, h;
    asm("mov.b64 {%0, %1}, %2;" : "=r"(l), "=r"(h) : "l"(v));
    lo = __uint_as_float(l); hi = __uint_as_float(h);
}

// ---------------------------------------------------------------------------
// Grouped 3x3 conv (groups=4, in=out=256ch), stride 1, pad 1. Both sides in
// one launch: z = s*8 + b*4 + g.
// Each block processes TWO 8-row bands sequentially (yt loop) -> 192 blocks
// total = single resident wave at 2 blocks/SM (no tail-wave waste).
// MODE 1: input = BN(cat[side]) on load; output = leaky(conv + bias)
// MODE 2: input = t1[side]; output = conv + bias + BN(cat[side]) residual
// Per band: tile 8 rows x 32 cols x 64 oc; 256 threads; f32x2 math;
// weights staged as tap-pairs (ulonglong2) -> LDS.128 broadcast loads.
// ---------------------------------------------------------------------------
constexpr int TH   = 8;
constexpr int TW   = 32;
constexpr int ICB  = 8;
constexpr int INROW   = TW + 2;   // 34 valid cols
constexpr int INPITCH = 36;       // even pitch -> float2-aligned rows

constexpr int WOCSTR    = ICB * 10;                // 80 ull per oc (10-slot taps)
constexpr int CONV_W2   = 64 * WOCSTR;             // 5120 ull = 40960 B
constexpr int CONV_IN   = ICB * 10 * INPITCH;      // float count
constexpr int CONV_SMEM = CONV_W2 * 8 + CONV_IN * 4 + 2 * 64 * 4;

template <int MODE>
__global__ __launch_bounds__(256, 2)
void conv3x3_kernel(const float* __restrict__ catL,
                    const float* __restrict__ catR,
                    const float* __restrict__ tin,
                    const float* __restrict__ wgt,   // (256, 64, 3, 3)
                    const float* __restrict__ bias,  // (256)
                    const float* __restrict__ bn_g,
                    const float* __restrict__ bn_b,
                    const float* __restrict__ bn_m,
                    const float* __restrict__ bn_v,
                    float* __restrict__ out)
{
    extern __shared__ unsigned char csm[];
    ull*   s_w2 = (ull*)csm;                       // [oc*80 + c*10 + tap]
    float* s_in = (float*)(s_w2 + CONV_W2);        // [c][10][36]
    float* s_sc = s_in + CONV_IN;
    float* s_sh = s_sc + 64;

    const int tid = threadIdx.x;
    const int bz  = blockIdx.z;        // s*8 + b*4 + g
    const int s   = bz >> 3;
    const int b   = (bz >> 2) & 1;
    const int g   = bz & 3;
    const int sb  = s * B_ + b;
    const int x0  = blockIdx.x * TW;
    const int chbase = g * 64;

    const float* cat = s ? catR : catL;

    if (tid < 64) {
        const int ch = chbase + tid;
        const float sc = bn_g[ch] * rsqrtf(bn_v[ch] + 1e-5f);
        s_sc[tid] = sc;
        s_sh[tid] = bn_b[ch] - bn_m[ch] * sc;
    }

    const int og   = tid >> 5;        // 0..7 (out-channel octet)
    const int p    = tid & 31;
    const int rowp = p >> 2;          // 0..7
    const int colp = (p & 3) * 8;     // 0,8,16,24

    const float* inb = (MODE == 1)
        ? cat + (size_t)(b * C4_ + chbase) * HW_
        : tin + (size_t)(sb * C4_ + chbase) * HW_;
    const float* catb = cat + (size_t)(b * C4_ + chbase) * HW_;
    float*       outb = out + (size_t)(sb * C4_ + chbase) * HW_;

    __syncthreads();  // s_sc/s_sh ready

#pragma unroll 1
    for (int yt = 0; yt < 2; yt++) {
        const int y0 = blockIdx.y * (2 * TH) + yt * TH;

        ull acc2[8][4];
#pragma unroll
        for (int o = 0; o < 8; o++)
#pragma unroll
            for (int q = 0; q < 4; q++) acc2[o][q] = 0ULL;

        for (int icb = 0; icb < 64; icb += ICB) {
            // stage input tile (BN on load for MODE 1)
            for (int idx = tid; idx < ICB * 10 * INROW; idx += 256) {
                const int c   = idx / (10 * INROW);
                const int rem = idx % (10 * INROW);
                const int r   = rem / INROW;
                const int cc  = rem % INROW;
                const int gy  = y0 - 1 + r;
                const int gx  = x0 - 1 + cc;
                float v = 0.f;
                if ((unsigned)gy < (unsigned)H_ && (unsigned)gx < (unsigned)W_) {
                    v = inb[(size_t)(icb + c) * HW_ + gy * W_ + gx];
                    if (MODE == 1) v = v * s_sc[icb + c] + s_sh[icb + c];
                }
                s_in[(c * 10 + r) * INPITCH + cc] = v;
            }
            // stage weights duplicated into f32x2, 10-slot tap axis (slot 9 pad)
            for (int idx = tid; idx < CONV_W2; idx += 256) {
                const int oc  = idx / WOCSTR;
                const int r   = idx % WOCSTR;    // c*10 + tap
                const int c   = r / 10;
                const int tap = r % 10;
                float w = 0.f;
                if (tap < 9)
                    w = wgt[(size_t)(chbase + oc) * 576 + (icb + c) * 9 + tap];
                s_w2[oc * WOCSTR + r] = pk2(w, w);
            }
            __syncthreads();

#pragma unroll 2
            for (int c = 0; c < ICB; c++) {
                float xv[3][10];
#pragma unroll
                for (int kh = 0; kh < 3; kh++) {
                    const float* rp = &s_in[(c * 10 + rowp + kh) * INPITCH + colp];
#pragma unroll
                    for (int t5 = 0; t5 < 5; t5++) {
                        const float2 v = ((const float2*)rp)[t5];
                        xv[kh][2 * t5]     = v.x;
                        xv[kh][2 * t5 + 1] = v.y;
                    }
                }
                // tap-pair loop: one LDS.128 delivers weights for 2 taps
                const ulonglong2* wb2 =
                    (const ulonglong2*)&s_w2[(og * 8) * WOCSTR + c * 10];
#pragma unroll
                for (int tp = 0; tp < 5; tp++) {
                    const int t0  = 2 * tp;
                    const int kh0 = t0 / 3, tc0 = t0 % 3;
                    ull xa[4];
#pragma unroll
                    for (int q = 0; q < 4; q++)
                        xa[q] = pk2(xv[kh0][tc0 + 2 * q], xv[kh0][tc0 + 2 * q + 1]);
                    ull xb[4];
                    if (tp < 4) {
                        const int t1  = t0 + 1;
                        const int kh1 = t1 / 3, tc1 = t1 % 3;
#pragma unroll
                        for (int q = 0; q < 4; q++)
                            xb[q] = pk2(xv[kh1][tc1 + 2 * q], xv[kh1][tc1 + 2 * q + 1]);
                    }
#pragma unroll
                    for (int o = 0; o < 8; o++) {
                        const ulonglong2 w = wb2[o * (WOCSTR / 2) + tp];  // LDS.128
                        fma2(acc2[o][0], w.x, xa[0]);
                        fma2(acc2[o][1], w.x, xa[1]);
                        fma2(acc2[o][2], w.x, xa[2]);
                        fma2(acc2[o][3], w.x, xa[3]);
                        if (tp < 4) {
                            fma2(acc2[o][0], w.y, xb[0]);
                            fma2(acc2[o][1], w.y, xb[1]);
                            fma2(acc2[o][2], w.y, xb[2]);
                            fma2(acc2[o][3], w.y, xb[3]);
                        }
                    }
                }
            }
            __syncthreads();
        }

        // epilogue for this band (registers + global only; safe vs next band's
        // staging because compute already synced and s_sc/s_sh are read-only)
        const int y = y0 + rowp;
#pragma unroll
        for (int o = 0; o < 8; o++) {
            const int oc = og * 8 + o;
            const float bv = bias[chbase + oc];
#pragma unroll
            for (int pq = 0; pq < 4; pq++) {
                float v0, v1;
                unpk2(acc2[o][pq], v0, v1);
#pragma unroll
                for (int half = 0; half < 2; half++) {
                    const int x = x0 + colp + 2 * pq + half;
                    float v = (half ? v1 : v0) + bv;
                    if (MODE == 1) {
                        v = (v > 0.f) ? v : 0.1f * v;         // LeakyReLU(0.1)
                    } else {
                        const float cv = catb[(size_t)oc * HW_ + y * W_ + x];
                        v += cv * s_sc[oc] + s_sh[oc];
                    }
                    outb[(size_t)oc * HW_ + y * W_ + x] = v;
                }
            }
        }
    }
}

// ---------------------------------------------------------------------------
// Grouped 1x1 conv: 64oc <- 256ic, groups=4 (16oc per group reads 64ic).
// z = s*8 + b*4 + g. Each thread: 4 consecutive pixels, all 16 oc.
// Weights as oc-pairs -> LDS.128 broadcast.
// ---------------------------------------------------------------------------
__global__ __launch_bounds__(256)
void conv1x1_kernel(const float* __restrict__ in,    // t2 [sb][256][HW]
                    const float* __restrict__ bqw, const float* __restrict__ bqb,
                    const float* __restrict__ bsw, const float* __restrict__ bsb,
                    float* __restrict__ Qb, float* __restrict__ Kb)
{
    __shared__ ulonglong2 s_wt2[64 * 8];   // [ic][ocpair], 8KB

    const int tid = threadIdx.x;
    const int bz  = blockIdx.z;
    const int s   = bz >> 3;
    const int b   = (bz >> 2) & 1;
    const int g   = bz & 3;

    const float* wsel = s ? bsw : bqw;
    const float* bsel = s ? bsb : bqb;

    for (int idx = tid; idx < 512; idx += 256) {
        const int ic = idx >> 3;
        const int op = idx & 7;
        const float wa = wsel[(g * 16 + 2 * op)     * 64 + ic];
        const float wb = wsel[(g * 16 + 2 * op + 1) * 64 + ic];
        s_wt2[idx] = make_ulonglong2(pk2(wa, wa), pk2(wb, wb));
    }
    __syncthreads();

    const int px0 = blockIdx.x * 1024 + tid * 4;
    const float* ip = in + (size_t)((s * B_ + b) * C4_ + g * 64) * HW_ + px0;

    ull acc[16][2];
#pragma unroll
    for (int o = 0; o < 16; o++) {
        const float bv = bsel[g * 16 + o];
        acc[o][0] = pk2(bv, bv);
        acc[o][1] = pk2(bv, bv);
    }

    for (int ic = 0; ic < 64; ic++) {
        const float4 v = *(const float4*)&ip[(size_t)ic * HW_];
        const ull v01 = pk2(v.x, v.y);
        const ull v23 = pk2(v.z, v.w);
        const ulonglong2* wp = &s_wt2[ic * 8];
#pragma unroll
        for (int op = 0; op < 8; op++) {
            const ulonglong2 w = wp[op];          // LDS.128 broadcast
            fma2(acc[2 * op][0],     w.x, v01);
            fma2(acc[2 * op][1],     w.x, v23);
            fma2(acc[2 * op + 1][0], w.y, v01);
            fma2(acc[2 * op + 1][1], w.y, v23);
        }
    }

    float* op_ = (s ? Kb : Qb) + (size_t)(b * C_ + g * 16) * HW_ + px0;
#pragma unroll
    for (int o = 0; o < 16; o++) {
        float4 r;
        unpk2(acc[o][0], r.x, r.y);
        unpk2(acc[o][1], r.z, r.w);
        *(float4*)&op_[(size_t)o * HW_] = r;
    }
}

// ---------------------------------------------------------------------------
// Attention kernel (R5 measured-best config). Grid (H, B, dir). 256 threads.
// dir 0 = r2l (K-window/Q-center -> outL from xR)
// dir 1 = l2r (Q-window/K-center -> outR from xL, value coords still r2l).
// Window strips channel-paired as float2; 4-col zero padding -> no predicates.
// Mean subtraction dropped (softmax-invariant).
// ---------------------------------------------------------------------------
constexpr int ROWP2  = 105;             // row pitch in float2 units
constexpr int CSTR2  = 8 * ROWP2 + 5;   // 845, channel-pair stride (float2)
constexpr int NPAIR  = 4;               // channel pairs per chunk (8 channels)
constexpr int WIN_F2 = NPAIR * CSTR2;   // 3380 float2
constexpr int CEN_F2 = NPAIR * 96;      // 384 float2
constexpr int MPITCH = 66;
constexpr int M_F    = 96 * MPITCH;     // 6336 floats
constexpr int OUT_F  = 8 * 96;          // 768 floats
constexpr int ATT_SMEM = WIN_F2 * 8 + CEN_F2 * 8 + M_F * 4 + OUT_F * 4 + 5 * 96 * 4;

__global__ __launch_bounds__(256, 3)
void attention_kernel(const float* __restrict__ Qf, const float* __restrict__ Kf,
                      const float* __restrict__ xL, const float* __restrict__ xR,
                      const int* __restrict__ dL, const int* __restrict__ dR,
                      float* __restrict__ outL, float* __restrict__ outR)
{
    extern __shared__ float smem[];
    float2* s_win2 = (float2*)smem;                 // WIN_F2
    float2* s_cen2 = s_win2 + WIN_F2;               // CEN_F2
    float*  s_M    = (float*)(s_cen2 + CEN_F2);     // M_F
    float*  s_out  = s_M + M_F;                     // OUT_F
    int*    s_cc   = (int*)(s_out + OUT_F);         // 96  logits centers
    int*    s_cv   = s_cc + 96;                     // 96  value centers (= cr)
    int*    s_sval = s_cv + 96;                     // 96  softmax validity
    int*    s_vval = s_sval + 96;                   // 96  value validity (= vR)
    float*  s_mask = (float*)(s_vval + 96);         // 96  output mask

    const int i   = blockIdx.x;
    const int b   = blockIdx.y;
    const int z   = blockIdx.z;                     // 0=r2l, 1=l2r
    const int tid = threadIdx.x;

    if (tid < 96) {
        const int j  = tid;
        const int dl = dL[(b * H_ + i) * W_ + j];
        const int dr = dR[(b * H_ + i) * W_ + j];
        const int cr = max(j - dl, 0);
        const int cl = min(j + dr, W_ - 1);
        const int rowok = (i + 4) < H_;
        const int vR = (rowok && cr < W_ - 4) ? 1 : 0;
        const int vL = (rowok && cl < W_ - 4) ? 1 : 0;
        s_cc[j]   = z ? cl : cr;
        s_cv[j]   = cr;                             // value coords always r2l
        s_sval[j] = z ? vL : vR;
        s_vval[j] = vR;                             // value validity always vR
        s_mask[j] = z ? ((j + dr <= W_ - 1) ? 1.f : 0.f)
                      : ((j - dl >= 0)      ? 1.f : 0.f);
    }
    for (int idx = tid; idx < WIN_F2; idx += 256)
        s_win2[idx] = make_float2(0.f, 0.f);        // incl. pad columns
    for (int idx = tid; idx < M_F; idx += 256) s_M[idx] = 0.f;
    __syncthreads();

    const float* winsrc = z ? Qf : Kf;
    const float* censrc = z ? Kf : Qf;
    const int kbit  = tid & 1;
    const int koff  = kbit * 32;
    const int aoff2 = kbit * 4 * ROWP2;
    const int jlog  = tid >> 1;

    // ---- logits: 8 chunks of 4 channel pairs ----
    for (int cb = 0; cb < 8; cb++) {
        const int c0 = cb * 8;
        const float* wsb = winsrc + (size_t)(b * C_ + c0) * HW_;
        for (int idx = tid; idx < NPAIR * 768; idx += 256) {
            const int cp  = idx / 768;
            const int rem = idx - cp * 768;          // a*96 + col
            const int a   = rem / 96;
            const int col = rem - a * 96;
            const int gy  = i - 4 + a;
            float v0 = 0.f, v1 = 0.f;
            if ((unsigned)gy < (unsigned)H_) {
                const size_t o = (size_t)(2 * cp) * HW_ + gy * W_ + col;
                v0 = wsb[o];
                v1 = wsb[o + HW_];
            }
            s_win2[cp * CSTR2 + a * ROWP2 + 4 + col] = make_float2(v0, v1);
        }
        const float* csb = censrc + (size_t)(b * C_ + c0) * HW_ + (size_t)i * W_;
        for (int idx = tid; idx < NPAIR * 96; idx += 256) {
            const int cp = idx / 96, j = idx - cp * 96;
            const size_t o = (size_t)(2 * cp) * HW_ + j;
            s_cen2[idx] = make_float2(csb[o], csb[o + HW_]);
        }
        __syncthreads();

        if (tid < 192) {
            const int cc = s_cc[jlog];
            float acc[32];
#pragma unroll
            for (int kk = 0; kk < 32; kk++) acc[kk] = 0.f;
#pragma unroll
            for (int cp = 0; cp < NPAIR; cp++) {
                const float2 cen = s_cen2[cp * 96 + jlog];
                const float2* wb = s_win2 + cp * CSTR2 + cc + aoff2;
#pragma unroll
                for (int kk = 0; kk < 32; kk++) {
                    const float2 w = wb[(kk >> 3) * ROWP2 + (kk & 7)];
                    acc[kk] = fmaf(cen.x, w.x, fmaf(cen.y, w.y, acc[kk]));
                }
            }
            float* Mrow = s_M + jlog * MPITCH + koff;
#pragma unroll
            for (int kk = 0; kk < 32; kk++) Mrow[kk] += acc[kk];
        }
        __syncthreads();
    }

    // ---- softmax ----
    if (tid < 96) {
        float* row = s_M + tid * MPITCH;
        if (!s_sval[tid]) {
#pragma unroll
            for (int k = 0; k < 64; k++) row[k] = 1.f / 64.f;
        } else {
            float mx = row[0];
#pragma unroll
            for (int k = 1; k < 64; k++) mx = fmaxf(mx, row[k]);
            float ssum = 0.f;
#pragma unroll
            for (int k = 0; k < 64; k++) {
                const float e = __expf(row[k] - mx);
                row[k] = e; ssum += e;
            }
            const float inv = 1.f / ssum;
#pragma unroll
            for (int k = 0; k < 64; k++) row[k] *= inv;
        }
    }
    __syncthreads();

    // ---- value pass: 8 chunks of 4 channel pairs ----
    const float* valsrc  = z ? xL : xR;
    const float* basesrc = z ? xR : xL;
    float*       outdst  = z ? outR : outL;
    const int cpair = tid & 3;
    const int jg    = tid >> 2;          // 0..63

    for (int cb = 0; cb < 8; cb++) {
        const int c0 = cb * 8;
        const float* vsb = valsrc + (size_t)(b * C_ + c0) * HW_;
        for (int idx = tid; idx < NPAIR * 768; idx += 256) {
            const int cp  = idx / 768;
            const int rem = idx - cp * 768;
            const int a   = rem / 96;
            const int col = rem - a * 96;
            const int gy  = i - 4 + a;
            float v0 = 0.f, v1 = 0.f;
            if ((unsigned)gy < (unsigned)H_) {
                const size_t o = (size_t)(2 * cp) * HW_ + gy * W_ + col;
                v0 = vsb[o];
                v1 = vsb[o + HW_];
            }
            s_win2[cp * CSTR2 + a * ROWP2 + 4 + col] = make_float2(v0, v1);
        }
        __syncthreads();

#pragma unroll
        for (int m = 0; m < 2; m++) {
            const int j = jg + 64 * m;
            if (j < 96) {
                float aL = 0.f, aH = 0.f;
                if (s_vval[j]) {
                    const float2* wb   = s_win2 + cpair * CSTR2 + s_cv[j];
                    const float*  Mrow = s_M + j * MPITCH;
#pragma unroll
                    for (int kp = 0; kp < 32; kp++) {
                        const float2 mv = *(const float2*)(Mrow + 2 * kp);
                        const int k0 = 2 * kp, k1 = 2 * kp + 1;
                        const float2 w0 = wb[(k0 >> 3) * ROWP2 + (k0 & 7)];
                        const float2 w1 = wb[(k1 >> 3) * ROWP2 + (k1 & 7)];
                        aL = fmaf(mv.x, w0.x, fmaf(mv.y, w1.x, aL));
                        aH = fmaf(mv.x, w0.y, fmaf(mv.y, w1.y, aH));
                    }
                }
                s_out[(2 * cpair) * 96 + j]     = aL * s_mask[j];
                s_out[(2 * cpair + 1) * 96 + j] = aH * s_mask[j];
            }
        }
        __syncthreads();

        for (int t = 0; t < 3; t++) {
            const int idx = tid + t * 256;
            const int c = idx / 96, j = idx - c * 96;
            const size_t gidx = ((size_t)(b * C_ + c0 + c) * H_ + i) * W_ + j;
            outdst[gidx] = basesrc[gidx] + s_out[idx];
        }
        __syncthreads();
    }
}

// ---------------------------------------------------------------------------
// Host launcher
// ---------------------------------------------------------------------------
extern "C" void kernel_launch(void* const* d_in, const int* in_sizes, int n_in,
                              void* d_out, int out_size)
{
    const float *xL, *xR, *catL, *catR;
    const float *bng, *bnb, *bnm, *bnv, *w1, *b1, *w2, *b2, *bqw, *bqb, *bsw, *bsb;
    const int *dL, *dR;

    const bool dict_order = (n_in >= 18) && (in_sizes[4] == B_ * H_ * W_);
    if (dict_order) {
        xL   = (const float*)d_in[0];  xR   = (const float*)d_in[1];
        catL = (const float*)d_in[2];  catR = (const float*)d_in[3];
        dL   = (const int*)  d_in[4];  dR   = (const int*)  d_in[5];
        bng  = (const float*)d_in[6];  bnb  = (const float*)d_in[7];
        bnm  = (const float*)d_in[8];  bnv  = (const float*)d_in[9];
        w1   = (const float*)d_in[10]; b1   = (const float*)d_in[11];
        w2   = (const float*)d_in[12]; b2   = (const float*)d_in[13];
        bqw  = (const float*)d_in[14]; bqb  = (const float*)d_in[15];
        bsw  = (const float*)d_in[16]; bsb  = (const float*)d_in[17];
    } else {
        xL   = (const float*)d_in[0];  xR   = (const float*)d_in[1];
        catL = (const float*)d_in[2];  catR = (const float*)d_in[3];
        bng  = (const float*)d_in[4];  bnb  = (const float*)d_in[5];
        bnm  = (const float*)d_in[6];  bnv  = (const float*)d_in[7];
        w1   = (const float*)d_in[8];  b1   = (const float*)d_in[9];
        w2   = (const float*)d_in[10]; b2   = (const float*)d_in[11];
        bqw  = (const float*)d_in[12]; bqb  = (const float*)d_in[13];
        bsw  = (const float*)d_in[14]; bsb  = (const float*)d_in[15];
        dL   = (const int*)  d_in[16]; dR   = (const int*)  d_in[17];
    }

    float *t1, *t2, *Qb, *Kb;
    cudaGetSymbolAddress((void**)&t1, g_t1);
    cudaGetSymbolAddress((void**)&t2, g_t2);
    cudaGetSymbolAddress((void**)&Qb, g_Q);
    cudaGetSymbolAddress((void**)&Kb, g_K);

    cudaFuncSetAttribute(conv3x3_kernel<1>,
                         cudaFuncAttributeMaxDynamicSharedMemorySize, CONV_SMEM);
    cudaFuncSetAttribute(conv3x3_kernel<2>,
                         cudaFuncAttributeMaxDynamicSharedMemorySize, CONV_SMEM);
    cudaFuncSetAttribute(attention_kernel,
                         cudaFuncAttributeMaxDynamicSharedMemorySize, ATT_SMEM);

    // 2 row-bands per block: grid (3, 4, 16) = 192 blocks -> single wave @2/SM
    const dim3 cgrid(W_ / TW, H_ / (2 * TH), NSB * 4);

    conv3x3_kernel<1><<<cgrid, 256, CONV_SMEM>>>(catL, catR, nullptr, w1, b1,
                                                 bng, bnb, bnm, bnv, t1);
    conv3x3_kernel<2><<<cgrid, 256, CONV_SMEM>>>(catL, catR, t1, w2, b2,
                                                 bng, bnb, bnm, bnv, t2);
    conv1x1_kernel<<<dim3(6, 1, 16), 256>>>(t2, bqw, bqb, bsw, bsb, Qb, Kb);

    float* outL = (float*)d_out;
    float* outR = outL + (size_t)B_ * C_ * HW_;
    attention_kernel<<<dim3(H_, B_, 2), 256, ATT_SMEM>>>(Qb, Kb, xL, xR, dL, dR,
                                                         outL, outR);
}

// round 10
// speedup vs baseline: 1.2782x; 1.2782x over previous
#include <cuda_runtime.h>
#include <cstddef>

// ---------------------------------------------------------------------------
// Problem constants
// ---------------------------------------------------------------------------
constexpr int B_  = 2;
constexpr int C_  = 64;
constexpr int C4_ = 256;
constexpr int H_  = 64;
constexpr int W_  = 96;
constexpr int HW_ = H_ * W_;
constexpr int NSB = 2 * B_;   // side * batch slots

typedef unsigned long long ull;

// Scratch (device globals: no allocations allowed). Layout [side*B+b][C4][HW]
__device__ float g_t1[(size_t)NSB * C4_ * HW_];
__device__ float g_t2[(size_t)NSB * C4_ * HW_];
__device__ float g_Q [(size_t)B_ * C_  * HW_];
__device__ float g_K [(size_t)B_ * C_  * HW_];

// ---------------------------------------------------------------------------
// f32x2 helpers (sm_100+ packed fp32 — exact, two independent IEEE FMAs)
// ---------------------------------------------------------------------------
__device__ __forceinline__ ull pk2(float a, float b) {
    ull r;
    asm("mov.b64 %0, {%1, %2};" : "=l"(r)
        : "r"(__float_as_uint(a)), "r"(__float_as_uint(b)));
    return r;
}
__device__ __forceinline__ void fma2(ull& d, ull a, ull b) {
    asm("fma.rn.f32x2 %0, %1, %2, %0;" : "+l"(d) : "l"(a), "l"(b));
}
__device__ __forceinline__ void unpk2(ull v, float& lo, float& hi) {
    unsigned l, h;
    asm("mov.b64 {%0, %1}, %2;" : "=r"(l), "=r"(h) : "l"(v));
    lo = __uint_as_float(l); hi = __uint_as_float(h);
}

// ---------------------------------------------------------------------------
// Grouped 3x3 conv (groups=4, in=out=256ch), stride 1, pad 1.
// OC-SPLIT: each block computes 32 output channels (half a group) over the
// full 64-ic reduction for an 8x32 tile. z = (((s*2+b)*4+g)*2 + oh).
// 768 blocks, 3 blocks/SM (24 warps/SM). Per thread: 4 oc x 8 px.
// MODE 1: input = BN(cat[side]) on load; output = leaky(conv + bias)
// MODE 2: input = t1[side]; output = conv + bias + BN(cat[side]) residual
// ---------------------------------------------------------------------------
constexpr int TH   = 8;
constexpr int TW   = 32;
constexpr int ICB  = 8;
constexpr int INROW   = TW + 2;   // 34 valid cols
constexpr int INPITCH = 36;       // even pitch -> float2-aligned rows

constexpr int CONV_W2   = 32 * 72;                 // 2304 ull = 18432 B
constexpr int CONV_IN   = ICB * 10 * INPITCH;      // 2880 floats = 11520 B
constexpr int CONV_SMEM = CONV_W2 * 8 + CONV_IN * 4 + 2 * 64 * 4;  // ~30.5 KB

template <int MODE>
__global__ __launch_bounds__(256, 3)
void conv3x3_kernel(const float* __restrict__ catL,
                    const float* __restrict__ catR,
                    const float* __restrict__ tin,
                    const float* __restrict__ wgt,   // (256, 64, 3, 3)
                    const float* __restrict__ bias,  // (256)
                    const float* __restrict__ bn_g,
                    const float* __restrict__ bn_b,
                    const float* __restrict__ bn_m,
                    const float* __restrict__ bn_v,
                    float* __restrict__ out)
{
    extern __shared__ unsigned char csm[];
    ull*   s_w2 = (ull*)csm;                       // [oc*72 + c*9 + tap], oc<32
    float* s_in = (float*)(s_w2 + CONV_W2);        // [c][10][36]
    float* s_sc = s_in + CONV_IN;                  // per-channel-in-group BN
    float* s_sh = s_sc + 64;

    const int tid = threadIdx.x;
    const int bz  = blockIdx.z;        // (((s*2+b)*4+g)*2 + oh)
    const int oh  = bz & 1;
    const int g   = (bz >> 1) & 3;
    const int b   = (bz >> 3) & 1;
    const int s   = bz >> 4;
    const int sb  = s * B_ + b;
    const int y0  = blockIdx.y * TH;
    const int x0  = blockIdx.x * TW;
    const int gbase = g * 64;                      // input-channel group base
    const int obase = g * 64 + oh * 32;            // output-channel base

    const float* cat = s ? catR : catL;

    if (tid < 64) {
        const int ch = gbase + tid;
        const float sc = bn_g[ch] * rsqrtf(bn_v[ch] + 1e-5f);
        s_sc[tid] = sc;
        s_sh[tid] = bn_b[ch] - bn_m[ch] * sc;
    }

    const int og   = tid >> 5;        // 0..7 -> 4-oc group
    const int p    = tid & 31;
    const int rowp = p >> 2;          // 0..7
    const int colp = (p & 3) * 8;     // 0,8,16,24

    ull acc2[4][4];
#pragma unroll
    for (int o = 0; o < 4; o++)
#pragma unroll
        for (int q = 0; q < 4; q++) acc2[o][q] = 0ULL;

    const float* inb = (MODE == 1)
        ? cat + (size_t)(b * C4_ + gbase) * HW_
        : tin + (size_t)(sb * C4_ + gbase) * HW_;

    __syncthreads();  // s_sc/s_sh ready

    for (int icb = 0; icb < 64; icb += ICB) {
        // stage input tile (BN on load for MODE 1)
        for (int idx = tid; idx < ICB * 10 * INROW; idx += 256) {
            const int c   = idx / (10 * INROW);
            const int rem = idx % (10 * INROW);
            const int r   = rem / INROW;
            const int cc  = rem % INROW;
            const int gy  = y0 - 1 + r;
            const int gx  = x0 - 1 + cc;
            float v = 0.f;
            if ((unsigned)gy < (unsigned)H_ && (unsigned)gx < (unsigned)W_) {
                v = inb[(size_t)(icb + c) * HW_ + gy * W_ + gx];
                if (MODE == 1) v = v * s_sc[icb + c] + s_sh[icb + c];
            }
            s_in[(c * 10 + r) * INPITCH + cc] = v;
        }
        // stage weights (32 oc) duplicated into f32x2: s_w2[oc*72 + c*9 + tap]
        for (int idx = tid; idx < CONV_W2; idx += 256) {
            const int oc  = idx / 72;
            const int r   = idx % 72;    // c*9 + tap
            const int c   = r / 9;
            const int tap = r % 9;
            const float w = wgt[(size_t)(obase + oc) * 576 + (icb + c) * 9 + tap];
            s_w2[idx] = pk2(w, w);
        }
        __syncthreads();

#pragma unroll 2
        for (int c = 0; c < ICB; c++) {
            float xv[3][10];
#pragma unroll
            for (int kh = 0; kh < 3; kh++) {
                const float* rp = &s_in[(c * 10 + rowp + kh) * INPITCH + colp];
#pragma unroll
                for (int t5 = 0; t5 < 5; t5++) {
                    const float2 v = ((const float2*)rp)[t5];
                    xv[kh][2 * t5]     = v.x;
                    xv[kh][2 * t5 + 1] = v.y;
                }
            }
            const ull* wbase = &s_w2[(og * 4) * 72 + c * 9];
#pragma unroll
            for (int kh = 0; kh < 3; kh++) {
#pragma unroll
                for (int t = 0; t < 3; t++) {
                    const int tap = kh * 3 + t;
                    const ull xp0 = pk2(xv[kh][t],     xv[kh][t + 1]);
                    const ull xp1 = pk2(xv[kh][t + 2], xv[kh][t + 3]);
                    const ull xp2 = pk2(xv[kh][t + 4], xv[kh][t + 5]);
                    const ull xp3 = pk2(xv[kh][t + 6], xv[kh][t + 7]);
#pragma unroll
                    for (int o = 0; o < 4; o++) {
                        const ull w = wbase[o * 72 + tap];   // LDS.64 broadcast
                        fma2(acc2[o][0], w, xp0);
                        fma2(acc2[o][1], w, xp1);
                        fma2(acc2[o][2], w, xp2);
                        fma2(acc2[o][3], w, xp3);
                    }
                }
            }
        }
        __syncthreads();
    }

    // epilogue
    const float* catb = cat + (size_t)(b * C4_ + obase) * HW_;
    float*       outb = out + (size_t)(sb * C4_ + obase) * HW_;
    const int y = y0 + rowp;
#pragma unroll
    for (int o = 0; o < 4; o++) {
        const int oc  = og * 4 + o;            // 0..31 within this half
        const int cig = oh * 32 + oc;          // channel-in-group for BN
        const float bv = bias[obase + oc];
#pragma unroll
        for (int pq = 0; pq < 4; pq++) {
            float v0, v1;
            unpk2(acc2[o][pq], v0, v1);
#pragma unroll
            for (int half = 0; half < 2; half++) {
                const int x = x0 + colp + 2 * pq + half;
                float v = (half ? v1 : v0) + bv;
                if (MODE == 1) {
                    v = (v > 0.f) ? v : 0.1f * v;         // LeakyReLU(0.1)
                } else {
                    const float cv = catb[(size_t)oc * HW_ + y * W_ + x];
                    v += cv * s_sc[cig] + s_sh[cig];
                }
                outb[(size_t)oc * HW_ + y * W_ + x] = v;
            }
        }
    }
}

// ---------------------------------------------------------------------------
// Grouped 1x1 conv: 64oc <- 256ic, groups=4 (16oc per group reads 64ic).
// z = s*8 + b*4 + g. Each thread: 4 consecutive pixels, all 16 oc.
// Weights as oc-pairs -> LDS.128 broadcast.
// ---------------------------------------------------------------------------
__global__ __launch_bounds__(256)
void conv1x1_kernel(const float* __restrict__ in,    // t2 [sb][256][HW]
                    const float* __restrict__ bqw, const float* __restrict__ bqb,
                    const float* __restrict__ bsw, const float* __restrict__ bsb,
                    float* __restrict__ Qb, float* __restrict__ Kb)
{
    __shared__ ulonglong2 s_wt2[64 * 8];   // [ic][ocpair], 8KB

    const int tid = threadIdx.x;
    const int bz  = blockIdx.z;
    const int s   = bz >> 3;
    const int b   = (bz >> 2) & 1;
    const int g   = bz & 3;

    const float* wsel = s ? bsw : bqw;
    const float* bsel = s ? bsb : bqb;

    for (int idx = tid; idx < 512; idx += 256) {
        const int ic = idx >> 3;
        const int op = idx & 7;
        const float wa = wsel[(g * 16 + 2 * op)     * 64 + ic];
        const float wb = wsel[(g * 16 + 2 * op + 1) * 64 + ic];
        s_wt2[idx] = make_ulonglong2(pk2(wa, wa), pk2(wb, wb));
    }
    __syncthreads();

    const int px0 = blockIdx.x * 1024 + tid * 4;
    const float* ip = in + (size_t)((s * B_ + b) * C4_ + g * 64) * HW_ + px0;

    ull acc[16][2];
#pragma unroll
    for (int o = 0; o < 16; o++) {
        const float bv = bsel[g * 16 + o];
        acc[o][0] = pk2(bv, bv);
        acc[o][1] = pk2(bv, bv);
    }

    for (int ic = 0; ic < 64; ic++) {
        const float4 v = *(const float4*)&ip[(size_t)ic * HW_];
        const ull v01 = pk2(v.x, v.y);
        const ull v23 = pk2(v.z, v.w);
        const ulonglong2* wp = &s_wt2[ic * 8];
#pragma unroll
        for (int op = 0; op < 8; op++) {
            const ulonglong2 w = wp[op];          // LDS.128 broadcast
            fma2(acc[2 * op][0],     w.x, v01);
            fma2(acc[2 * op][1],     w.x, v23);
            fma2(acc[2 * op + 1][0], w.y, v01);
            fma2(acc[2 * op + 1][1], w.y, v23);
        }
    }

    float* op_ = (s ? Kb : Qb) + (size_t)(b * C_ + g * 16) * HW_ + px0;
#pragma unroll
    for (int o = 0; o < 16; o++) {
        float4 r;
        unpk2(acc[o][0], r.x, r.y);
        unpk2(acc[o][1], r.z, r.w);
        *(float4*)&op_[(size_t)o * HW_] = r;
    }
}

// ---------------------------------------------------------------------------
// Attention kernel (measured-best config, 105.8us). Grid (H, B, dir).
// dir 0 = r2l (K-window/Q-center -> outL from xR)
// dir 1 = l2r (Q-window/K-center -> outR from xL, value coords still r2l).
// Window strips channel-paired as float2; 4-col zero padding -> no predicates.
// Mean subtraction dropped (softmax-invariant).
// ---------------------------------------------------------------------------
constexpr int ROWP2  = 105;             // row pitch in float2 units
constexpr int CSTR2  = 8 * ROWP2 + 5;   // 845, channel-pair stride (float2)
constexpr int NPAIR  = 4;               // channel pairs per chunk (8 channels)
constexpr int WIN_F2 = NPAIR * CSTR2;   // 3380 float2
constexpr int CEN_F2 = NPAIR * 96;      // 384 float2
constexpr int MPITCH = 66;
constexpr int M_F    = 96 * MPITCH;     // 6336 floats
constexpr int OUT_F  = 8 * 96;          // 768 floats
constexpr int ATT_SMEM = WIN_F2 * 8 + CEN_F2 * 8 + M_F * 4 + OUT_F * 4 + 5 * 96 * 4;

__global__ __launch_bounds__(256, 3)
void attention_kernel(const float* __restrict__ Qf, const float* __restrict__ Kf,
                      const float* __restrict__ xL, const float* __restrict__ xR,
                      const int* __restrict__ dL, const int* __restrict__ dR,
                      float* __restrict__ outL, float* __restrict__ outR)
{
    extern __shared__ float smem[];
    float2* s_win2 = (float2*)smem;                 // WIN_F2
    float2* s_cen2 = s_win2 + WIN_F2;               // CEN_F2
    float*  s_M    = (float*)(s_cen2 + CEN_F2);     // M_F
    float*  s_out  = s_M + M_F;                     // OUT_F
    int*    s_cc   = (int*)(s_out + OUT_F);         // 96  logits centers
    int*    s_cv   = s_cc + 96;                     // 96  value centers (= cr)
    int*    s_sval = s_cv + 96;                     // 96  softmax validity
    int*    s_vval = s_sval + 96;                   // 96  value validity (= vR)
    float*  s_mask = (float*)(s_vval + 96);         // 96  output mask

    const int i   = blockIdx.x;
    const int b   = blockIdx.y;
    const int z   = blockIdx.z;                     // 0=r2l, 1=l2r
    const int tid = threadIdx.x;

    if (tid < 96) {
        const int j  = tid;
        const int dl = dL[(b * H_ + i) * W_ + j];
        const int dr = dR[(b * H_ + i) * W_ + j];
        const int cr = max(j - dl, 0);
        const int cl = min(j + dr, W_ - 1);
        const int rowok = (i + 4) < H_;
        const int vR = (rowok && cr < W_ - 4) ? 1 : 0;
        const int vL = (rowok && cl < W_ - 4) ? 1 : 0;
        s_cc[j]   = z ? cl : cr;
        s_cv[j]   = cr;                             // value coords always r2l
        s_sval[j] = z ? vL : vR;
        s_vval[j] = vR;                             // value validity always vR
        s_mask[j] = z ? ((j + dr <= W_ - 1) ? 1.f : 0.f)
                      : ((j - dl >= 0)      ? 1.f : 0.f);
    }
    for (int idx = tid; idx < WIN_F2; idx += 256)
        s_win2[idx] = make_float2(0.f, 0.f);        // incl. pad columns
    for (int idx = tid; idx < M_F; idx += 256) s_M[idx] = 0.f;
    __syncthreads();

    const float* winsrc = z ? Qf : Kf;
    const float* censrc = z ? Kf : Qf;
    const int kbit  = tid & 1;
    const int koff  = kbit * 32;
    const int aoff2 = kbit * 4 * ROWP2;
    const int jlog  = tid >> 1;

    // ---- logits: 8 chunks of 4 channel pairs ----
    for (int cb = 0; cb < 8; cb++) {
        const int c0 = cb * 8;
        const float* wsb = winsrc + (size_t)(b * C_ + c0) * HW_;
        for (int idx = tid; idx < NPAIR * 768; idx += 256) {
            const int cp  = idx / 768;
            const int rem = idx - cp * 768;          // a*96 + col
            const int a   = rem / 96;
            const int col = rem - a * 96;
            const int gy  = i - 4 + a;
            float v0 = 0.f, v1 = 0.f;
            if ((unsigned)gy < (unsigned)H_) {
                const size_t o = (size_t)(2 * cp) * HW_ + gy * W_ + col;
                v0 = wsb[o];
                v1 = wsb[o + HW_];
            }
            s_win2[cp * CSTR2 + a * ROWP2 + 4 + col] = make_float2(v0, v1);
        }
        const float* csb = censrc + (size_t)(b * C_ + c0) * HW_ + (size_t)i * W_;
        for (int idx = tid; idx < NPAIR * 96; idx += 256) {
            const int cp = idx / 96, j = idx - cp * 96;
            const size_t o = (size_t)(2 * cp) * HW_ + j;
            s_cen2[idx] = make_float2(csb[o], csb[o + HW_]);
        }
        __syncthreads();

        if (tid < 192) {
            const int cc = s_cc[jlog];
            float acc[32];
#pragma unroll
            for (int kk = 0; kk < 32; kk++) acc[kk] = 0.f;
#pragma unroll
            for (int cp = 0; cp < NPAIR; cp++) {
                const float2 cen = s_cen2[cp * 96 + jlog];
                const float2* wb = s_win2 + cp * CSTR2 + cc + aoff2;
#pragma unroll
                for (int kk = 0; kk < 32; kk++) {
                    const float2 w = wb[(kk >> 3) * ROWP2 + (kk & 7)];
                    acc[kk] = fmaf(cen.x, w.x, fmaf(cen.y, w.y, acc[kk]));
                }
            }
            float* Mrow = s_M + jlog * MPITCH + koff;
#pragma unroll
            for (int kk = 0; kk < 32; kk++) Mrow[kk] += acc[kk];
        }
        __syncthreads();
    }

    // ---- softmax ----
    if (tid < 96) {
        float* row = s_M + tid * MPITCH;
        if (!s_sval[tid]) {
#pragma unroll
            for (int k = 0; k < 64; k++) row[k] = 1.f / 64.f;
        } else {
            float mx = row[0];
#pragma unroll
            for (int k = 1; k < 64; k++) mx = fmaxf(mx, row[k]);
            float ssum = 0.f;
#pragma unroll
            for (int k = 0; k < 64; k++) {
                const float e = __expf(row[k] - mx);
                row[k] = e; ssum += e;
            }
            const float inv = 1.f / ssum;
#pragma unroll
            for (int k = 0; k < 64; k++) row[k] *= inv;
        }
    }
    __syncthreads();

    // ---- value pass: 8 chunks of 4 channel pairs ----
    const float* valsrc  = z ? xL : xR;
    const float* basesrc = z ? xR : xL;
    float*       outdst  = z ? outR : outL;
    const int cpair = tid & 3;
    const int jg    = tid >> 2;          // 0..63

    for (int cb = 0; cb < 8; cb++) {
        const int c0 = cb * 8;
        const float* vsb = valsrc + (size_t)(b * C_ + c0) * HW_;
        for (int idx = tid; idx < NPAIR * 768; idx += 256) {
            const int cp  = idx / 768;
            const int rem = idx - cp * 768;
            const int a   = rem / 96;
            const int col = rem - a * 96;
            const int gy  = i - 4 + a;
            float v0 = 0.f, v1 = 0.f;
            if ((unsigned)gy < (unsigned)H_) {
                const size_t o = (size_t)(2 * cp) * HW_ + gy * W_ + col;
                v0 = vsb[o];
                v1 = vsb[o + HW_];
            }
            s_win2[cp * CSTR2 + a * ROWP2 + 4 + col] = make_float2(v0, v1);
        }
        __syncthreads();

#pragma unroll
        for (int m = 0; m < 2; m++) {
            const int j = jg + 64 * m;
            if (j < 96) {
                float aL = 0.f, aH = 0.f;
                if (s_vval[j]) {
                    const float2* wb   = s_win2 + cpair * CSTR2 + s_cv[j];
                    const float*  Mrow = s_M + j * MPITCH;
#pragma unroll
                    for (int kp = 0; kp < 32; kp++) {
                        const float2 mv = *(const float2*)(Mrow + 2 * kp);
                        const int k0 = 2 * kp, k1 = 2 * kp + 1;
                        const float2 w0 = wb[(k0 >> 3) * ROWP2 + (k0 & 7)];
                        const float2 w1 = wb[(k1 >> 3) * ROWP2 + (k1 & 7)];
                        aL = fmaf(mv.x, w0.x, fmaf(mv.y, w1.x, aL));
                        aH = fmaf(mv.x, w0.y, fmaf(mv.y, w1.y, aH));
                    }
                }
                s_out[(2 * cpair) * 96 + j]     = aL * s_mask[j];
                s_out[(2 * cpair + 1) * 96 + j] = aH * s_mask[j];
            }
        }
        __syncthreads();

        for (int t = 0; t < 3; t++) {
            const int idx = tid + t * 256;
            const int c = idx / 96, j = idx - c * 96;
            const size_t gidx = ((size_t)(b * C_ + c0 + c) * H_ + i) * W_ + j;
            outdst[gidx] = basesrc[gidx] + s_out[idx];
        }
        __syncthreads();
    }
}

// ---------------------------------------------------------------------------
// Host launcher
// ---------------------------------------------------------------------------
extern "C" void kernel_launch(void* const* d_in, const int* in_sizes, int n_in,
                              void* d_out, int out_size)
{
    const float *xL, *xR, *catL, *catR;
    const float *bng, *bnb, *bnm, *bnv, *w1, *b1, *w2, *b2, *bqw, *bqb, *bsw, *bsb;
    const int *dL, *dR;

    const bool dict_order = (n_in >= 18) && (in_sizes[4] == B_ * H_ * W_);
    if (dict_order) {
        xL   = (const float*)d_in[0];  xR   = (const float*)d_in[1];
        catL = (const float*)d_in[2];  catR = (const float*)d_in[3];
        dL   = (const int*)  d_in[4];  dR   = (const int*)  d_in[5];
        bng  = (const float*)d_in[6];  bnb  = (const float*)d_in[7];
        bnm  = (const float*)d_in[8];  bnv  = (const float*)d_in[9];
        w1   = (const float*)d_in[10]; b1   = (const float*)d_in[11];
        w2   = (const float*)d_in[12]; b2   = (const float*)d_in[13];
        bqw  = (const float*)d_in[14]; bqb  = (const float*)d_in[15];
        bsw  = (const float*)d_in[16]; bsb  = (const float*)d_in[17];
    } else {
        xL   = (const float*)d_in[0];  xR   = (const float*)d_in[1];
        catL = (const float*)d_in[2];  catR = (const float*)d_in[3];
        bng  = (const float*)d_in[4];  bnb  = (const float*)d_in[5];
        bnm  = (const float*)d_in[6];  bnv  = (const float*)d_in[7];
        w1   = (const float*)d_in[8];  b1   = (const float*)d_in[9];
        w2   = (const float*)d_in[10]; b2   = (const float*)d_in[11];
        bqw  = (const float*)d_in[12]; bqb  = (const float*)d_in[13];
        bsw  = (const float*)d_in[14]; bsb  = (const float*)d_in[15];
        dL   = (const int*)  d_in[16]; dR   = (const int*)  d_in[17];
    }

    float *t1, *t2, *Qb, *Kb;
    cudaGetSymbolAddress((void**)&t1, g_t1);
    cudaGetSymbolAddress((void**)&t2, g_t2);
    cudaGetSymbolAddress((void**)&Qb, g_Q);
    cudaGetSymbolAddress((void**)&Kb, g_K);

    cudaFuncSetAttribute(conv3x3_kernel<1>,
                         cudaFuncAttributeMaxDynamicSharedMemorySize, CONV_SMEM);
    cudaFuncSetAttribute(conv3x3_kernel<2>,
                         cudaFuncAttributeMaxDynamicSharedMemorySize, CONV_SMEM);
    cudaFuncSetAttribute(attention_kernel,
                         cudaFuncAttributeMaxDynamicSharedMemorySize, ATT_SMEM);

    // oc-split: grid (3, 8, 32) = 768 blocks, 3 blocks/SM
    const dim3 cgrid(W_ / TW, H_ / TH, NSB * 8);

    conv3x3_kernel<1><<<cgrid, 256, CONV_SMEM>>>(catL, catR, nullptr, w1, b1,
                                                 bng, bnb, bnm, bnv, t1);
    conv3x3_kernel<2><<<cgrid, 256, CONV_SMEM>>>(catL, catR, t1, w2, b2,
                                                 bng, bnb, bnm, bnv, t2);
    conv1x1_kernel<<<dim3(6, 1, 16), 256>>>(t2, bqw, bqb, bsw, bsb, Qb, Kb);

    float* outL = (float*)d_out;
    float* outR = outL + (size_t)B_ * C_ * HW_;
    attention_kernel<<<dim3(H_, B_, 2), 256, ATT_SMEM>>>(Qb, Kb, xL, xR, dL, dR,
                                                         outL, outR);
}

// round 11
// speedup vs baseline: 1.3390x; 1.0476x over previous
#include <cuda_runtime.h>
#include <cstddef>

// ---------------------------------------------------------------------------
// Problem constants
// ---------------------------------------------------------------------------
constexpr int B_  = 2;
constexpr int C_  = 64;
constexpr int C4_ = 256;
constexpr int H_  = 64;
constexpr int W_  = 96;
constexpr int HW_ = H_ * W_;
constexpr int NSB = 2 * B_;   // side * batch slots

typedef unsigned long long ull;

// Scratch (device globals: no allocations allowed). Layout [side*B+b][C4][HW]
__device__ float g_t1[(size_t)NSB * C4_ * HW_];
__device__ float g_t2[(size_t)NSB * C4_ * HW_];
__device__ float g_Q [(size_t)B_ * C_  * HW_];
__device__ float g_K [(size_t)B_ * C_  * HW_];

// ---------------------------------------------------------------------------
// f32x2 helpers (sm_100+ packed fp32 — exact, two independent IEEE FMAs)
// ---------------------------------------------------------------------------
__device__ __forceinline__ ull pk2(float a, float b) {
    ull r;
    asm("mov.b64 %0, {%1, %2};" : "=l"(r)
        : "r"(__float_as_uint(a)), "r"(__float_as_uint(b)));
    return r;
}
__device__ __forceinline__ void fma2(ull& d, ull a, ull b) {
    asm("fma.rn.f32x2 %0, %1, %2, %0;" : "+l"(d) : "l"(a), "l"(b));
}
__device__ __forceinline__ void unpk2(ull v, float& lo, float& hi) {
    unsigned l, h;
    asm("mov.b64 {%0, %1}, %2;" : "=r"(l), "=r"(h) : "l"(v));
    lo = __uint_as_float(l); hi = __uint_as_float(h);
}

// ---------------------------------------------------------------------------
// Grouped 3x3 conv (R10 measured-best — FROZEN).
// OC-SPLIT: each block computes 32 output channels (half a group) over the
// full 64-ic reduction for an 8x32 tile. z = (((s*2+b)*4+g)*2 + oh).
// 768 blocks, 3 blocks/SM. Per thread: 4 oc x 8 px.
// ---------------------------------------------------------------------------
constexpr int TH   = 8;
constexpr int TW   = 32;
constexpr int ICB  = 8;
constexpr int INROW   = TW + 2;   // 34 valid cols
constexpr int INPITCH = 36;       // even pitch -> float2-aligned rows

constexpr int CONV_W2   = 32 * 72;                 // 2304 ull = 18432 B
constexpr int CONV_IN   = ICB * 10 * INPITCH;      // 2880 floats = 11520 B
constexpr int CONV_SMEM = CONV_W2 * 8 + CONV_IN * 4 + 2 * 64 * 4;  // ~30.5 KB

template <int MODE>
__global__ __launch_bounds__(256, 3)
void conv3x3_kernel(const float* __restrict__ catL,
                    const float* __restrict__ catR,
                    const float* __restrict__ tin,
                    const float* __restrict__ wgt,   // (256, 64, 3, 3)
                    const float* __restrict__ bias,  // (256)
                    const float* __restrict__ bn_g,
                    const float* __restrict__ bn_b,
                    const float* __restrict__ bn_m,
                    const float* __restrict__ bn_v,
                    float* __restrict__ out)
{
    extern __shared__ unsigned char csm[];
    ull*   s_w2 = (ull*)csm;                       // [oc*72 + c*9 + tap], oc<32
    float* s_in = (float*)(s_w2 + CONV_W2);        // [c][10][36]
    float* s_sc = s_in + CONV_IN;                  // per-channel-in-group BN
    float* s_sh = s_sc + 64;

    const int tid = threadIdx.x;
    const int bz  = blockIdx.z;        // (((s*2+b)*4+g)*2 + oh)
    const int oh  = bz & 1;
    const int g   = (bz >> 1) & 3;
    const int b   = (bz >> 3) & 1;
    const int s   = bz >> 4;
    const int sb  = s * B_ + b;
    const int y0  = blockIdx.y * TH;
    const int x0  = blockIdx.x * TW;
    const int gbase = g * 64;                      // input-channel group base
    const int obase = g * 64 + oh * 32;            // output-channel base

    const float* cat = s ? catR : catL;

    if (tid < 64) {
        const int ch = gbase + tid;
        const float sc = bn_g[ch] * rsqrtf(bn_v[ch] + 1e-5f);
        s_sc[tid] = sc;
        s_sh[tid] = bn_b[ch] - bn_m[ch] * sc;
    }

    const int og   = tid >> 5;        // 0..7 -> 4-oc group
    const int p    = tid & 31;
    const int rowp = p >> 2;          // 0..7
    const int colp = (p & 3) * 8;     // 0,8,16,24

    ull acc2[4][4];
#pragma unroll
    for (int o = 0; o < 4; o++)
#pragma unroll
        for (int q = 0; q < 4; q++) acc2[o][q] = 0ULL;

    const float* inb = (MODE == 1)
        ? cat + (size_t)(b * C4_ + gbase) * HW_
        : tin + (size_t)(sb * C4_ + gbase) * HW_;

    __syncthreads();  // s_sc/s_sh ready

    for (int icb = 0; icb < 64; icb += ICB) {
        // stage input tile (BN on load for MODE 1)
        for (int idx = tid; idx < ICB * 10 * INROW; idx += 256) {
            const int c   = idx / (10 * INROW);
            const int rem = idx % (10 * INROW);
            const int r   = rem / INROW;
            const int cc  = rem % INROW;
            const int gy  = y0 - 1 + r;
            const int gx  = x0 - 1 + cc;
            float v = 0.f;
            if ((unsigned)gy < (unsigned)H_ && (unsigned)gx < (unsigned)W_) {
                v = inb[(size_t)(icb + c) * HW_ + gy * W_ + gx];
                if (MODE == 1) v = v * s_sc[icb + c] + s_sh[icb + c];
            }
            s_in[(c * 10 + r) * INPITCH + cc] = v;
        }
        // stage weights (32 oc) duplicated into f32x2: s_w2[oc*72 + c*9 + tap]
        for (int idx = tid; idx < CONV_W2; idx += 256) {
            const int oc  = idx / 72;
            const int r   = idx % 72;    // c*9 + tap
            const int c   = r / 9;
            const int tap = r % 9;
            const float w = wgt[(size_t)(obase + oc) * 576 + (icb + c) * 9 + tap];
            s_w2[idx] = pk2(w, w);
        }
        __syncthreads();

#pragma unroll 2
        for (int c = 0; c < ICB; c++) {
            float xv[3][10];
#pragma unroll
            for (int kh = 0; kh < 3; kh++) {
                const float* rp = &s_in[(c * 10 + rowp + kh) * INPITCH + colp];
#pragma unroll
                for (int t5 = 0; t5 < 5; t5++) {
                    const float2 v = ((const float2*)rp)[t5];
                    xv[kh][2 * t5]     = v.x;
                    xv[kh][2 * t5 + 1] = v.y;
                }
            }
            const ull* wbase = &s_w2[(og * 4) * 72 + c * 9];
#pragma unroll
            for (int kh = 0; kh < 3; kh++) {
#pragma unroll
                for (int t = 0; t < 3; t++) {
                    const int tap = kh * 3 + t;
                    const ull xp0 = pk2(xv[kh][t],     xv[kh][t + 1]);
                    const ull xp1 = pk2(xv[kh][t + 2], xv[kh][t + 3]);
                    const ull xp2 = pk2(xv[kh][t + 4], xv[kh][t + 5]);
                    const ull xp3 = pk2(xv[kh][t + 6], xv[kh][t + 7]);
#pragma unroll
                    for (int o = 0; o < 4; o++) {
                        const ull w = wbase[o * 72 + tap];   // LDS.64 broadcast
                        fma2(acc2[o][0], w, xp0);
                        fma2(acc2[o][1], w, xp1);
                        fma2(acc2[o][2], w, xp2);
                        fma2(acc2[o][3], w, xp3);
                    }
                }
            }
        }
        __syncthreads();
    }

    // epilogue
    const float* catb = cat + (size_t)(b * C4_ + obase) * HW_;
    float*       outb = out + (size_t)(sb * C4_ + obase) * HW_;
    const int y = y0 + rowp;
#pragma unroll
    for (int o = 0; o < 4; o++) {
        const int oc  = og * 4 + o;            // 0..31 within this half
        const int cig = oh * 32 + oc;          // channel-in-group for BN
        const float bv = bias[obase + oc];
#pragma unroll
        for (int pq = 0; pq < 4; pq++) {
            float v0, v1;
            unpk2(acc2[o][pq], v0, v1);
#pragma unroll
            for (int half = 0; half < 2; half++) {
                const int x = x0 + colp + 2 * pq + half;
                float v = (half ? v1 : v0) + bv;
                if (MODE == 1) {
                    v = (v > 0.f) ? v : 0.1f * v;         // LeakyReLU(0.1)
                } else {
                    const float cv = catb[(size_t)oc * HW_ + y * W_ + x];
                    v += cv * s_sc[cig] + s_sh[cig];
                }
                outb[(size_t)oc * HW_ + y * W_ + x] = v;
            }
        }
    }
}

// ---------------------------------------------------------------------------
// Grouped 1x1 conv (FROZEN).
// ---------------------------------------------------------------------------
__global__ __launch_bounds__(256)
void conv1x1_kernel(const float* __restrict__ in,    // t2 [sb][256][HW]
                    const float* __restrict__ bqw, const float* __restrict__ bqb,
                    const float* __restrict__ bsw, const float* __restrict__ bsb,
                    float* __restrict__ Qb, float* __restrict__ Kb)
{
    __shared__ ulonglong2 s_wt2[64 * 8];   // [ic][ocpair], 8KB

    const int tid = threadIdx.x;
    const int bz  = blockIdx.z;
    const int s   = bz >> 3;
    const int b   = (bz >> 2) & 1;
    const int g   = bz & 3;

    const float* wsel = s ? bsw : bqw;
    const float* bsel = s ? bsb : bqb;

    for (int idx = tid; idx < 512; idx += 256) {
        const int ic = idx >> 3;
        const int op = idx & 7;
        const float wa = wsel[(g * 16 + 2 * op)     * 64 + ic];
        const float wb = wsel[(g * 16 + 2 * op + 1) * 64 + ic];
        s_wt2[idx] = make_ulonglong2(pk2(wa, wa), pk2(wb, wb));
    }
    __syncthreads();

    const int px0 = blockIdx.x * 1024 + tid * 4;
    const float* ip = in + (size_t)((s * B_ + b) * C4_ + g * 64) * HW_ + px0;

    ull acc[16][2];
#pragma unroll
    for (int o = 0; o < 16; o++) {
        const float bv = bsel[g * 16 + o];
        acc[o][0] = pk2(bv, bv);
        acc[o][1] = pk2(bv, bv);
    }

    for (int ic = 0; ic < 64; ic++) {
        const float4 v = *(const float4*)&ip[(size_t)ic * HW_];
        const ull v01 = pk2(v.x, v.y);
        const ull v23 = pk2(v.z, v.w);
        const ulonglong2* wp = &s_wt2[ic * 8];
#pragma unroll
        for (int op = 0; op < 8; op++) {
            const ulonglong2 w = wp[op];          // LDS.128 broadcast
            fma2(acc[2 * op][0],     w.x, v01);
            fma2(acc[2 * op][1],     w.x, v23);
            fma2(acc[2 * op + 1][0], w.y, v01);
            fma2(acc[2 * op + 1][1], w.y, v23);
        }
    }

    float* op_ = (s ? Kb : Qb) + (size_t)(b * C_ + g * 16) * HW_ + px0;
#pragma unroll
    for (int o = 0; o < 16; o++) {
        float4 r;
        unpk2(acc[o][0], r.x, r.y);
        unpk2(acc[o][1], r.z, r.w);
        *(float4*)&op_[(size_t)o * HW_] = r;
    }
}

// ---------------------------------------------------------------------------
// Attention kernel v3: float4 channel-QUADS (one LDS.128 feeds 4 channels),
// 4 chunks of 16 channels, register-resident logit accumulators (s_M written
// once). Grid (H, B, dir). 256 threads, 2 blocks/SM (grid-limited anyway).
// dir 0 = r2l (K-window/Q-center -> outL from xR)
// dir 1 = l2r (Q-window/K-center -> outR from xL, value coords still r2l).
// 4-col zero padding -> no predicates. Mean subtraction dropped.
// ---------------------------------------------------------------------------
constexpr int ROWP4  = 105;             // row pitch in float4 units
constexpr int CSTR4  = 8 * ROWP4 + 5;   // 845, quad stride (float4)
constexpr int NQUAD  = 4;               // quads per chunk (16 channels)
constexpr int WIN_F4 = NQUAD * CSTR4;   // 3380 float4 = 54080 B
constexpr int CEN_F4 = NQUAD * 96;      // 384 float4 = 6144 B
constexpr int MPITCH = 66;
constexpr int M_F    = 96 * MPITCH;     // 6336 floats = 25344 B
constexpr int OUT_F  = 16 * 96;         // 1536 floats = 6144 B
constexpr int ATT_SMEM = WIN_F4 * 16 + CEN_F4 * 16 + M_F * 4 + OUT_F * 4 + 5 * 96 * 4;

__global__ __launch_bounds__(256, 2)
void attention_kernel(const float* __restrict__ Qf, const float* __restrict__ Kf,
                      const float* __restrict__ xL, const float* __restrict__ xR,
                      const int* __restrict__ dL, const int* __restrict__ dR,
                      float* __restrict__ outL, float* __restrict__ outR)
{
    extern __shared__ float smem[];
    float4* s_win4 = (float4*)smem;                 // WIN_F4
    float4* s_cen4 = s_win4 + WIN_F4;               // CEN_F4
    float*  s_M    = (float*)(s_cen4 + CEN_F4);     // M_F
    float*  s_out  = s_M + M_F;                     // OUT_F
    int*    s_cc   = (int*)(s_out + OUT_F);         // 96  logits centers
    int*    s_cv   = s_cc + 96;                     // 96  value centers (= cr)
    int*    s_sval = s_cv + 96;                     // 96  softmax validity
    int*    s_vval = s_sval + 96;                   // 96  value validity (= vR)
    float*  s_mask = (float*)(s_vval + 96);         // 96  output mask

    const int i   = blockIdx.x;
    const int b   = blockIdx.y;
    const int z   = blockIdx.z;                     // 0=r2l, 1=l2r
    const int tid = threadIdx.x;

    if (tid < 96) {
        const int j  = tid;
        const int dl = dL[(b * H_ + i) * W_ + j];
        const int dr = dR[(b * H_ + i) * W_ + j];
        const int cr = max(j - dl, 0);
        const int cl = min(j + dr, W_ - 1);
        const int rowok = (i + 4) < H_;
        const int vR = (rowok && cr < W_ - 4) ? 1 : 0;
        const int vL = (rowok && cl < W_ - 4) ? 1 : 0;
        s_cc[j]   = z ? cl : cr;
        s_cv[j]   = cr;                             // value coords always r2l
        s_sval[j] = z ? vL : vR;
        s_vval[j] = vR;                             // value validity always vR
        s_mask[j] = z ? ((j + dr <= W_ - 1) ? 1.f : 0.f)
                      : ((j - dl >= 0)      ? 1.f : 0.f);
    }
    const float4 zero4 = make_float4(0.f, 0.f, 0.f, 0.f);
    for (int idx = tid; idx < WIN_F4; idx += 256) s_win4[idx] = zero4;
    __syncthreads();

    const float* winsrc = z ? Qf : Kf;
    const float* censrc = z ? Kf : Qf;
    const int kbit  = tid & 1;
    const int koff  = kbit * 32;
    const int aoff4 = kbit * 4 * ROWP4;
    const int jlog  = tid >> 1;
    const int cc    = (tid < 192) ? s_cc[jlog] : 0;

    // ---- logits: 4 chunks of 4 channel quads; acc stays in registers ----
    float acc[32];
#pragma unroll
    for (int kk = 0; kk < 32; kk++) acc[kk] = 0.f;

    for (int cb = 0; cb < 4; cb++) {
        const int c0 = cb * 16;
        const float* wsb = winsrc + (size_t)(b * C_ + c0) * HW_;
        for (int idx = tid; idx < NQUAD * 768; idx += 256) {
            const int q   = idx / 768;
            const int rem = idx - q * 768;           // a*96 + col
            const int a   = rem / 96;
            const int col = rem - a * 96;
            const int gy  = i - 4 + a;
            float4 v = zero4;
            if ((unsigned)gy < (unsigned)H_) {
                const float* p = wsb + (size_t)(4 * q) * HW_ + gy * W_ + col;
                v.x = p[0]; v.y = p[HW_]; v.z = p[2 * HW_]; v.w = p[3 * HW_];
            }
            s_win4[q * CSTR4 + a * ROWP4 + 4 + col] = v;
        }
        const float* csb = censrc + (size_t)(b * C_ + c0) * HW_ + (size_t)i * W_;
        for (int idx = tid; idx < NQUAD * 96; idx += 256) {
            const int q = idx / 96, j = idx - q * 96;
            const float* p = csb + (size_t)(4 * q) * HW_ + j;
            s_cen4[idx] = make_float4(p[0], p[HW_], p[2 * HW_], p[3 * HW_]);
        }
        __syncthreads();

        if (tid < 192) {
#pragma unroll
            for (int q = 0; q < NQUAD; q++) {
                const float4 cen = s_cen4[q * 96 + jlog];
                const float4* wb = s_win4 + q * CSTR4 + cc + aoff4;
#pragma unroll
                for (int kk = 0; kk < 32; kk++) {
                    const float4 w = wb[(kk >> 3) * ROWP4 + (kk & 7)];
                    acc[kk] = fmaf(cen.x, w.x,
                              fmaf(cen.y, w.y,
                              fmaf(cen.z, w.z,
                              fmaf(cen.w, w.w, acc[kk]))));
                }
            }
        }
        __syncthreads();
    }

    if (tid < 192) {
        float* Mrow = s_M + jlog * MPITCH + koff;
#pragma unroll
        for (int kk = 0; kk < 32; kk++) Mrow[kk] = acc[kk];
    }
    __syncthreads();

    // ---- softmax ----
    if (tid < 96) {
        float* row = s_M + tid * MPITCH;
        if (!s_sval[tid]) {
#pragma unroll
            for (int k = 0; k < 64; k++) row[k] = 1.f / 64.f;
        } else {
            float mx = row[0];
#pragma unroll
            for (int k = 1; k < 64; k++) mx = fmaxf(mx, row[k]);
            float ssum = 0.f;
#pragma unroll
            for (int k = 0; k < 64; k++) {
                const float e = __expf(row[k] - mx);
                row[k] = e; ssum += e;
            }
            const float inv = 1.f / ssum;
#pragma unroll
            for (int k = 0; k < 64; k++) row[k] *= inv;
        }
    }
    __syncthreads();

    // ---- value pass: 4 chunks of 4 channel quads ----
    const float* valsrc  = z ? xL : xR;
    const float* basesrc = z ? xR : xL;
    float*       outdst  = z ? outR : outL;
    const int quad = tid & 3;
    const int jg   = tid >> 2;           // 0..63

    for (int cb = 0; cb < 4; cb++) {
        const int c0 = cb * 16;
        const float* vsb = valsrc + (size_t)(b * C_ + c0) * HW_;
        for (int idx = tid; idx < NQUAD * 768; idx += 256) {
            const int q   = idx / 768;
            const int rem = idx - q * 768;
            const int a   = rem / 96;
            const int col = rem - a * 96;
            const int gy  = i - 4 + a;
            float4 v = zero4;
            if ((unsigned)gy < (unsigned)H_) {
                const float* p = vsb + (size_t)(4 * q) * HW_ + gy * W_ + col;
                v.x = p[0]; v.y = p[HW_]; v.z = p[2 * HW_]; v.w = p[3 * HW_];
            }
            s_win4[q * CSTR4 + a * ROWP4 + 4 + col] = v;
        }
        __syncthreads();

#pragma unroll
        for (int m = 0; m < 2; m++) {
            const int j = jg + 64 * m;
            if (j < 96) {
                float a0 = 0.f, a1 = 0.f, a2 = 0.f, a3 = 0.f;
                if (s_vval[j]) {
                    const float4* wb   = s_win4 + quad * CSTR4 + s_cv[j];
                    const float*  Mrow = s_M + j * MPITCH;
#pragma unroll
                    for (int kp = 0; kp < 32; kp++) {
                        const float2 mv = *(const float2*)(Mrow + 2 * kp);
                        const int k0 = 2 * kp, k1 = 2 * kp + 1;
                        const float4 w0 = wb[(k0 >> 3) * ROWP4 + (k0 & 7)];
                        const float4 w1 = wb[(k1 >> 3) * ROWP4 + (k1 & 7)];
                        a0 = fmaf(mv.x, w0.x, fmaf(mv.y, w1.x, a0));
                        a1 = fmaf(mv.x, w0.y, fmaf(mv.y, w1.y, a1));
                        a2 = fmaf(mv.x, w0.z, fmaf(mv.y, w1.z, a2));
                        a3 = fmaf(mv.x, w0.w, fmaf(mv.y, w1.w, a3));
                    }
                }
                const float mk = s_mask[j];
                s_out[(4 * quad + 0) * 96 + j] = a0 * mk;
                s_out[(4 * quad + 1) * 96 + j] = a1 * mk;
                s_out[(4 * quad + 2) * 96 + j] = a2 * mk;
                s_out[(4 * quad + 3) * 96 + j] = a3 * mk;
            }
        }
        __syncthreads();

        for (int t = 0; t < 6; t++) {
            const int idx = tid + t * 256;
            const int c = idx / 96, j = idx - c * 96;
            const size_t gidx = ((size_t)(b * C_ + c0 + c) * H_ + i) * W_ + j;
            outdst[gidx] = basesrc[gidx] + s_out[idx];
        }
        __syncthreads();
    }
}

// ---------------------------------------------------------------------------
// Host launcher
// ---------------------------------------------------------------------------
extern "C" void kernel_launch(void* const* d_in, const int* in_sizes, int n_in,
                              void* d_out, int out_size)
{
    const float *xL, *xR, *catL, *catR;
    const float *bng, *bnb, *bnm, *bnv, *w1, *b1, *w2, *b2, *bqw, *bqb, *bsw, *bsb;
    const int *dL, *dR;

    const bool dict_order = (n_in >= 18) && (in_sizes[4] == B_ * H_ * W_);
    if (dict_order) {
        xL   = (const float*)d_in[0];  xR   = (const float*)d_in[1];
        catL = (const float*)d_in[2];  catR = (const float*)d_in[3];
        dL   = (const int*)  d_in[4];  dR   = (const int*)  d_in[5];
        bng  = (const float*)d_in[6];  bnb  = (const float*)d_in[7];
        bnm  = (const float*)d_in[8];  bnv  = (const float*)d_in[9];
        w1   = (const float*)d_in[10]; b1   = (const float*)d_in[11];
        w2   = (const float*)d_in[12]; b2   = (const float*)d_in[13];
        bqw  = (const float*)d_in[14]; bqb  = (const float*)d_in[15];
        bsw  = (const float*)d_in[16]; bsb  = (const float*)d_in[17];
    } else {
        xL   = (const float*)d_in[0];  xR   = (const float*)d_in[1];
        catL = (const float*)d_in[2];  catR = (const float*)d_in[3];
        bng  = (const float*)d_in[4];  bnb  = (const float*)d_in[5];
        bnm  = (const float*)d_in[6];  bnv  = (const float*)d_in[7];
        w1   = (const float*)d_in[8];  b1   = (const float*)d_in[9];
        w2   = (const float*)d_in[10]; b2   = (const float*)d_in[11];
        bqw  = (const float*)d_in[12]; bqb  = (const float*)d_in[13];
        bsw  = (const float*)d_in[14]; bsb  = (const float*)d_in[15];
        dL   = (const int*)  d_in[16]; dR   = (const int*)  d_in[17];
    }

    float *t1, *t2, *Qb, *Kb;
    cudaGetSymbolAddress((void**)&t1, g_t1);
    cudaGetSymbolAddress((void**)&t2, g_t2);
    cudaGetSymbolAddress((void**)&Qb, g_Q);
    cudaGetSymbolAddress((void**)&Kb, g_K);

    cudaFuncSetAttribute(conv3x3_kernel<1>,
                         cudaFuncAttributeMaxDynamicSharedMemorySize, CONV_SMEM);
    cudaFuncSetAttribute(conv3x3_kernel<2>,
                         cudaFuncAttributeMaxDynamicSharedMemorySize, CONV_SMEM);
    cudaFuncSetAttribute(attention_kernel,
                         cudaFuncAttributeMaxDynamicSharedMemorySize, ATT_SMEM);

    // oc-split: grid (3, 8, 32) = 768 blocks, 3 blocks/SM
    const dim3 cgrid(W_ / TW, H_ / TH, NSB * 8);

    conv3x3_kernel<1><<<cgrid, 256, CONV_SMEM>>>(catL, catR, nullptr, w1, b1,
                                                 bng, bnb, bnm, bnv, t1);
    conv3x3_kernel<2><<<cgrid, 256, CONV_SMEM>>>(catL, catR, t1, w2, b2,
                                                 bng, bnb, bnm, bnv, t2);
    conv1x1_kernel<<<dim3(6, 1, 16), 256>>>(t2, bqw, bqb, bsw, bsb, Qb, Kb);

    float* outL = (float*)d_out;
    float* outR = outL + (size_t)B_ * C_ * HW_;
    attention_kernel<<<dim3(H_, B_, 2), 256, ATT_SMEM>>>(Qb, Kb, xL, xR, dL, dR,
                                                         outL, outR);
}

// round 14
// speedup vs baseline: 1.3540x; 1.0112x over previous
#include <cuda_runtime.h>
#include <cstddef>

// ---------------------------------------------------------------------------
// Problem constants
// ---------------------------------------------------------------------------
constexpr int B_  = 2;
constexpr int C_  = 64;
constexpr int C4_ = 256;
constexpr int H_  = 64;
constexpr int W_  = 96;
constexpr int HW_ = H_ * W_;
constexpr int NSB = 2 * B_;   // side * batch slots

typedef unsigned long long ull;

// Scratch (device globals: no allocations allowed). Layout [side*B+b][C4][HW]
__device__ float g_t1[(size_t)NSB * C4_ * HW_];
__device__ float g_t2[(size_t)NSB * C4_ * HW_];
__device__ float g_Q [(size_t)B_ * C_  * HW_];
__device__ float g_K [(size_t)B_ * C_  * HW_];

// ---------------------------------------------------------------------------
// f32x2 helpers (sm_100+ packed fp32 — exact, two independent IEEE FMAs)
// ---------------------------------------------------------------------------
__device__ __forceinline__ ull pk2(float a, float b) {
    ull r;
    asm("mov.b64 %0, {%1, %2};" : "=l"(r)
        : "r"(__float_as_uint(a)), "r"(__float_as_uint(b)));
    return r;
}
__device__ __forceinline__ void fma2(ull& d, ull a, ull b) {
    asm("fma.rn.f32x2 %0, %1, %2, %0;" : "+l"(d) : "l"(a), "l"(b));
}
__device__ __forceinline__ void unpk2(ull v, float& lo, float& hi) {
    unsigned l, h;
    asm("mov.b64 {%0, %1}, %2;" : "=r"(l), "=r"(h) : "l"(v));
    lo = __uint_as_float(l); hi = __uint_as_float(h);
}

// ---------------------------------------------------------------------------
// Grouped 3x3 conv (groups=4, in=out=256ch), stride 1, pad 1.
// OC-SPLIT (R10): 32 oc per block, 8x32 tile, 768 blocks, 3 blocks/SM.
// Batched unrolled staging (all LDGs into registers first -> MLP~20, then
// all STS). MODE1 applies BN per element in staging (boundary-correct:
// padded taps stay exactly 0, matching conv(pad(BN(x)))).
// MODE 2 epilogue: conv + bias + BN(cat) residual (uses s_sc/s_sh).
// ---------------------------------------------------------------------------
constexpr int TH   = 8;
constexpr int TW   = 32;
constexpr int ICB  = 8;
constexpr int INROW   = TW + 2;   // 34 valid cols
constexpr int INPITCH = 36;       // even pitch -> float2-aligned rows

constexpr int IN_ELEMS  = ICB * 10 * INROW;        // 2720
constexpr int CONV_W2   = 32 * 72;                 // 2304 ull = 18432 B
constexpr int CONV_IN   = ICB * 10 * INPITCH;      // 2880 floats = 11520 B
constexpr int CONV_SMEM = CONV_W2 * 8 + CONV_IN * 4 + 2 * 64 * 4;  // ~30.5 KB

template <int MODE>
__global__ __launch_bounds__(256, 3)
void conv3x3_kernel(const float* __restrict__ catL,
                    const float* __restrict__ catR,
                    const float* __restrict__ tin,
                    const float* __restrict__ wgt,   // (256, 64, 3, 3)
                    const float* __restrict__ bias,  // (256)
                    const float* __restrict__ bn_g,
                    const float* __restrict__ bn_b,
                    const float* __restrict__ bn_m,
                    const float* __restrict__ bn_v,
                    float* __restrict__ out)
{
    extern __shared__ unsigned char csm[];
    ull*   s_w2 = (ull*)csm;                       // [oc*72 + c*9 + tap], oc<32
    float* s_in = (float*)(s_w2 + CONV_W2);        // [c][10][36]
    float* s_sc = s_in + CONV_IN;                  // per-channel-in-group BN
    float* s_sh = s_sc + 64;

    const int tid = threadIdx.x;
    const int bz  = blockIdx.z;        // (((s*2+b)*4+g)*2 + oh)
    const int oh  = bz & 1;
    const int g   = (bz >> 1) & 3;
    const int b   = (bz >> 3) & 1;
    const int s   = bz >> 4;
    const int sb  = s * B_ + b;
    const int y0  = blockIdx.y * TH;
    const int x0  = blockIdx.x * TW;
    const int gbase = g * 64;                      // input-channel group base
    const int obase = g * 64 + oh * 32;            // output-channel base

    const float* cat = s ? catR : catL;

    if (tid < 64) {
        const int ch = gbase + tid;
        const float sc = bn_g[ch] * rsqrtf(bn_v[ch] + 1e-5f);
        s_sc[tid] = sc;
        s_sh[tid] = bn_b[ch] - bn_m[ch] * sc;
    }

    const int og   = tid >> 5;        // 0..7 -> 4-oc group
    const int p    = tid & 31;
    const int rowp = p >> 2;          // 0..7
    const int colp = (p & 3) * 8;     // 0,8,16,24

    ull acc2[4][4];
#pragma unroll
    for (int o = 0; o < 4; o++)
#pragma unroll
        for (int q = 0; q < 4; q++) acc2[o][q] = 0ULL;

    const float* inb = (MODE == 1)
        ? cat + (size_t)(b * C4_ + gbase) * HW_
        : tin + (size_t)(sb * C4_ + gbase) * HW_;

    __syncthreads();  // s_sc/s_sh ready

    for (int icb = 0; icb < 64; icb += ICB) {
        // -------- batched staging: all LDGs first (MLP ~20), then STS ----
        float rin[11];
        int   rc [11];   // channel index for BN apply
        bool  rok[11];   // in-bounds flag
#pragma unroll
        for (int t = 0; t < 11; t++) {
            const int idx = tid + t * 256;
            float v = 0.f;
            int   c = 0;
            bool  ok = false;
            if (idx < IN_ELEMS) {
                c = idx / 340;                    // 10*34
                const int rem = idx - c * 340;
                const int r   = rem / 34;
                const int cc  = rem - r * 34;
                const int gy  = y0 - 1 + r;
                const int gx  = x0 - 1 + cc;
                if ((unsigned)gy < (unsigned)H_ && (unsigned)gx < (unsigned)W_) {
                    v = inb[(size_t)(icb + c) * HW_ + gy * W_ + gx];
                    ok = true;
                }
            }
            rin[t] = v; rc[t] = c; rok[t] = ok;
        }
        float rwv[9];
#pragma unroll
        for (int t = 0; t < 9; t++) {
            const int idx = tid + t * 256;        // < 2304 always
            const int oc  = idx / 72;
            const int r   = idx - oc * 72;        // c*9 + tap
            const int c   = r / 9;
            const int tap = r - c * 9;
            rwv[t] = wgt[(size_t)(obase + oc) * 576 + (icb + c) * 9 + tap];
        }
        // BN per element (boundary-correct: only in-bounds values shifted)
        if (MODE == 1) {
#pragma unroll
            for (int t = 0; t < 11; t++)
                if (rok[t])
                    rin[t] = rin[t] * s_sc[icb + rc[t]] + s_sh[icb + rc[t]];
        }
#pragma unroll
        for (int t = 0; t < 11; t++) {
            const int idx = tid + t * 256;
            if (idx < IN_ELEMS) {
                const int c   = idx / 340;
                const int rem = idx - c * 340;
                const int r   = rem / 34;
                const int cc  = rem - r * 34;
                s_in[(c * 10 + r) * INPITCH + cc] = rin[t];
            }
        }
#pragma unroll
        for (int t = 0; t < 9; t++)
            s_w2[tid + t * 256] = pk2(rwv[t], rwv[t]);
        __syncthreads();

        // -------- compute --------
#pragma unroll 2
        for (int c = 0; c < ICB; c++) {
            float xv[3][10];
#pragma unroll
            for (int kh = 0; kh < 3; kh++) {
                const float* rp = &s_in[(c * 10 + rowp + kh) * INPITCH + colp];
#pragma unroll
                for (int t5 = 0; t5 < 5; t5++) {
                    const float2 v = ((const float2*)rp)[t5];
                    xv[kh][2 * t5]     = v.x;
                    xv[kh][2 * t5 + 1] = v.y;
                }
            }
            const ull* wbase = &s_w2[(og * 4) * 72 + c * 9];
#pragma unroll
            for (int kh = 0; kh < 3; kh++) {
#pragma unroll
                for (int t = 0; t < 3; t++) {
                    const int tap = kh * 3 + t;
                    const ull xp0 = pk2(xv[kh][t],     xv[kh][t + 1]);
                    const ull xp1 = pk2(xv[kh][t + 2], xv[kh][t + 3]);
                    const ull xp2 = pk2(xv[kh][t + 4], xv[kh][t + 5]);
                    const ull xp3 = pk2(xv[kh][t + 6], xv[kh][t + 7]);
#pragma unroll
                    for (int o = 0; o < 4; o++) {
                        const ull w = wbase[o * 72 + tap];   // LDS.64 broadcast
                        fma2(acc2[o][0], w, xp0);
                        fma2(acc2[o][1], w, xp1);
                        fma2(acc2[o][2], w, xp2);
                        fma2(acc2[o][3], w, xp3);
                    }
                }
            }
        }
        __syncthreads();
    }

    // epilogue
    const float* catb = cat + (size_t)(b * C4_ + obase) * HW_;
    float*       outb = out + (size_t)(sb * C4_ + obase) * HW_;
    const int y = y0 + rowp;
#pragma unroll
    for (int o = 0; o < 4; o++) {
        const int oc  = og * 4 + o;            // 0..31 within this half
        const int cig = oh * 32 + oc;          // channel-in-group for BN
        const float bv = bias[obase + oc];
#pragma unroll
        for (int pq = 0; pq < 4; pq++) {
            float v0, v1;
            unpk2(acc2[o][pq], v0, v1);
#pragma unroll
            for (int half = 0; half < 2; half++) {
                const int x = x0 + colp + 2 * pq + half;
                float v = (half ? v1 : v0) + bv;
                if (MODE == 1) {
                    v = (v > 0.f) ? v : 0.1f * v;         // LeakyReLU(0.1)
                } else {
                    const float cv = catb[(size_t)oc * HW_ + y * W_ + x];
                    v += cv * s_sc[cig] + s_sh[cig];
                }
                outb[(size_t)oc * HW_ + y * W_ + x] = v;
            }
        }
    }
}

// ---------------------------------------------------------------------------
// Grouped 1x1 conv (FROZEN).
// ---------------------------------------------------------------------------
__global__ __launch_bounds__(256)
void conv1x1_kernel(const float* __restrict__ in,    // t2 [sb][256][HW]
                    const float* __restrict__ bqw, const float* __restrict__ bqb,
                    const float* __restrict__ bsw, const float* __restrict__ bsb,
                    float* __restrict__ Qb, float* __restrict__ Kb)
{
    __shared__ ulonglong2 s_wt2[64 * 8];   // [ic][ocpair], 8KB

    const int tid = threadIdx.x;
    const int bz  = blockIdx.z;
    const int s   = bz >> 3;
    const int b   = (bz >> 2) & 1;
    const int g   = bz & 3;

    const float* wsel = s ? bsw : bqw;
    const float* bsel = s ? bsb : bqb;

    for (int idx = tid; idx < 512; idx += 256) {
        const int ic = idx >> 3;
        const int op = idx & 7;
        const float wa = wsel[(g * 16 + 2 * op)     * 64 + ic];
        const float wb = wsel[(g * 16 + 2 * op + 1) * 64 + ic];
        s_wt2[idx] = make_ulonglong2(pk2(wa, wa), pk2(wb, wb));
    }
    __syncthreads();

    const int px0 = blockIdx.x * 1024 + tid * 4;
    const float* ip = in + (size_t)((s * B_ + b) * C4_ + g * 64) * HW_ + px0;

    ull acc[16][2];
#pragma unroll
    for (int o = 0; o < 16; o++) {
        const float bv = bsel[g * 16 + o];
        acc[o][0] = pk2(bv, bv);
        acc[o][1] = pk2(bv, bv);
    }

    for (int ic = 0; ic < 64; ic++) {
        const float4 v = *(const float4*)&ip[(size_t)ic * HW_];
        const ull v01 = pk2(v.x, v.y);
        const ull v23 = pk2(v.z, v.w);
        const ulonglong2* wp = &s_wt2[ic * 8];
#pragma unroll
        for (int op = 0; op < 8; op++) {
            const ulonglong2 w = wp[op];          // LDS.128 broadcast
            fma2(acc[2 * op][0],     w.x, v01);
            fma2(acc[2 * op][1],     w.x, v23);
            fma2(acc[2 * op + 1][0], w.y, v01);
            fma2(acc[2 * op + 1][1], w.y, v23);
        }
    }

    float* op_ = (s ? Kb : Qb) + (size_t)(b * C_ + g * 16) * HW_ + px0;
#pragma unroll
    for (int o = 0; o < 16; o++) {
        float4 r;
        unpk2(acc[o][0], r.x, r.y);
        unpk2(acc[o][1], r.z, r.w);
        *(float4*)&op_[(size_t)o * HW_] = r;
    }
}

// ---------------------------------------------------------------------------
// Attention kernel v3 (R11 measured-best — FROZEN). float4 channel-quads,
// register-resident logit accumulators. Grid (H, B, dir).
// ---------------------------------------------------------------------------
constexpr int ROWP4  = 105;             // row pitch in float4 units
constexpr int CSTR4  = 8 * ROWP4 + 5;   // 845, quad stride (float4)
constexpr int NQUAD  = 4;               // quads per chunk (16 channels)
constexpr int WIN_F4 = NQUAD * CSTR4;   // 3380 float4 = 54080 B
constexpr int CEN_F4 = NQUAD * 96;      // 384 float4 = 6144 B
constexpr int MPITCH = 66;
constexpr int M_F    = 96 * MPITCH;     // 6336 floats = 25344 B
constexpr int OUT_F  = 16 * 96;         // 1536 floats = 6144 B
constexpr int ATT_SMEM = WIN_F4 * 16 + CEN_F4 * 16 + M_F * 4 + OUT_F * 4 + 5 * 96 * 4;

__global__ __launch_bounds__(256, 2)
void attention_kernel(const float* __restrict__ Qf, const float* __restrict__ Kf,
                      const float* __restrict__ xL, const float* __restrict__ xR,
                      const int* __restrict__ dL, const int* __restrict__ dR,
                      float* __restrict__ outL, float* __restrict__ outR)
{
    extern __shared__ float smem[];
    float4* s_win4 = (float4*)smem;                 // WIN_F4
    float4* s_cen4 = s_win4 + WIN_F4;               // CEN_F4
    float*  s_M    = (float*)(s_cen4 + CEN_F4);     // M_F
    float*  s_out  = s_M + M_F;                     // OUT_F
    int*    s_cc   = (int*)(s_out + OUT_F);         // 96  logits centers
    int*    s_cv   = s_cc + 96;                     // 96  value centers (= cr)
    int*    s_sval = s_cv + 96;                     // 96  softmax validity
    int*    s_vval = s_sval + 96;                   // 96  value validity (= vR)
    float*  s_mask = (float*)(s_vval + 96);         // 96  output mask

    const int i   = blockIdx.x;
    const int b   = blockIdx.y;
    const int z   = blockIdx.z;                     // 0=r2l, 1=l2r
    const int tid = threadIdx.x;

    if (tid < 96) {
        const int j  = tid;
        const int dl = dL[(b * H_ + i) * W_ + j];
        const int dr = dR[(b * H_ + i) * W_ + j];
        const int cr = max(j - dl, 0);
        const int cl = min(j + dr, W_ - 1);
        const int rowok = (i + 4) < H_;
        const int vR = (rowok && cr < W_ - 4) ? 1 : 0;
        const int vL = (rowok && cl < W_ - 4) ? 1 : 0;
        s_cc[j]   = z ? cl : cr;
        s_cv[j]   = cr;                             // value coords always r2l
        s_sval[j] = z ? vL : vR;
        s_vval[j] = vR;                             // value validity always vR
        s_mask[j] = z ? ((j + dr <= W_ - 1) ? 1.f : 0.f)
                      : ((j - dl >= 0)      ? 1.f : 0.f);
    }
    const float4 zero4 = make_float4(0.f, 0.f, 0.f, 0.f);
    for (int idx = tid; idx < WIN_F4; idx += 256) s_win4[idx] = zero4;
    __syncthreads();

    const float* winsrc = z ? Qf : Kf;
    const float* censrc = z ? Kf : Qf;
    const int kbit  = tid & 1;
    const int koff  = kbit * 32;
    const int aoff4 = kbit * 4 * ROWP4;
    const int jlog  = tid >> 1;
    const int cc    = (tid < 192) ? s_cc[jlog] : 0;

    // ---- logits: 4 chunks of 4 channel quads; acc stays in registers ----
    float acc[32];
#pragma unroll
    for (int kk = 0; kk < 32; kk++) acc[kk] = 0.f;

    for (int cb = 0; cb < 4; cb++) {
        const int c0 = cb * 16;
        const float* wsb = winsrc + (size_t)(b * C_ + c0) * HW_;
        for (int idx = tid; idx < NQUAD * 768; idx += 256) {
            const int q   = idx / 768;
            const int rem = idx - q * 768;           // a*96 + col
            const int a   = rem / 96;
            const int col = rem - a * 96;
            const int gy  = i - 4 + a;
            float4 v = zero4;
            if ((unsigned)gy < (unsigned)H_) {
                const float* p = wsb + (size_t)(4 * q) * HW_ + gy * W_ + col;
                v.x = p[0]; v.y = p[HW_]; v.z = p[2 * HW_]; v.w = p[3 * HW_];
            }
            s_win4[q * CSTR4 + a * ROWP4 + 4 + col] = v;
        }
        const float* csb = censrc + (size_t)(b * C_ + c0) * HW_ + (size_t)i * W_;
        for (int idx = tid; idx < NQUAD * 96; idx += 256) {
            const int q = idx / 96, j = idx - q * 96;
            const float* p = csb + (size_t)(4 * q) * HW_ + j;
            s_cen4[idx] = make_float4(p[0], p[HW_], p[2 * HW_], p[3 * HW_]);
        }
        __syncthreads();

        if (tid < 192) {
#pragma unroll
            for (int q = 0; q < NQUAD; q++) {
                const float4 cen = s_cen4[q * 96 + jlog];
                const float4* wb = s_win4 + q * CSTR4 + cc + aoff4;
#pragma unroll
                for (int kk = 0; kk < 32; kk++) {
                    const float4 w = wb[(kk >> 3) * ROWP4 + (kk & 7)];
                    acc[kk] = fmaf(cen.x, w.x,
                              fmaf(cen.y, w.y,
                              fmaf(cen.z, w.z,
                              fmaf(cen.w, w.w, acc[kk]))));
                }
            }
        }
        __syncthreads();
    }

    if (tid < 192) {
        float* Mrow = s_M + jlog * MPITCH + koff;
#pragma unroll
        for (int kk = 0; kk < 32; kk++) Mrow[kk] = acc[kk];
    }
    __syncthreads();

    // ---- softmax ----
    if (tid < 96) {
        float* row = s_M + tid * MPITCH;
        if (!s_sval[tid]) {
#pragma unroll
            for (int k = 0; k < 64; k++) row[k] = 1.f / 64.f;
        } else {
            float mx = row[0];
#pragma unroll
            for (int k = 1; k < 64; k++) mx = fmaxf(mx, row[k]);
            float ssum = 0.f;
#pragma unroll
            for (int k = 0; k < 64; k++) {
                const float e = __expf(row[k] - mx);
                row[k] = e; ssum += e;
            }
            const float inv = 1.f / ssum;
#pragma unroll
            for (int k = 0; k < 64; k++) row[k] *= inv;
        }
    }
    __syncthreads();

    // ---- value pass: 4 chunks of 4 channel quads ----
    const float* valsrc  = z ? xL : xR;
    const float* basesrc = z ? xR : xL;
    float*       outdst  = z ? outR : outL;
    const int quad = tid & 3;
    const int jg   = tid >> 2;           // 0..63

    for (int cb = 0; cb < 4; cb++) {
        const int c0 = cb * 16;
        const float* vsb = valsrc + (size_t)(b * C_ + c0) * HW_;
        for (int idx = tid; idx < NQUAD * 768; idx += 256) {
            const int q   = idx / 768;
            const int rem = idx - q * 768;
            const int a   = rem / 96;
            const int col = rem - a * 96;
            const int gy  = i - 4 + a;
            float4 v = zero4;
            if ((unsigned)gy < (unsigned)H_) {
                const float* p = vsb + (size_t)(4 * q) * HW_ + gy * W_ + col;
                v.x = p[0]; v.y = p[HW_]; v.z = p[2 * HW_]; v.w = p[3 * HW_];
            }
            s_win4[q * CSTR4 + a * ROWP4 + 4 + col] = v;
        }
        __syncthreads();

#pragma unroll
        for (int m = 0; m < 2; m++) {
            const int j = jg + 64 * m;
            if (j < 96) {
                float a0 = 0.f, a1 = 0.f, a2 = 0.f, a3 = 0.f;
                if (s_vval[j]) {
                    const float4* wb   = s_win4 + quad * CSTR4 + s_cv[j];
                    const float*  Mrow = s_M + j * MPITCH;
#pragma unroll
                    for (int kp = 0; kp < 32; kp++) {
                        const float2 mv = *(const float2*)(Mrow + 2 * kp);
                        const int k0 = 2 * kp, k1 = 2 * kp + 1;
                        const float4 w0 = wb[(k0 >> 3) * ROWP4 + (k0 & 7)];
                        const float4 w1 = wb[(k1 >> 3) * ROWP4 + (k1 & 7)];
                        a0 = fmaf(mv.x, w0.x, fmaf(mv.y, w1.x, a0));
                        a1 = fmaf(mv.x, w0.y, fmaf(mv.y, w1.y, a1));
                        a2 = fmaf(mv.x, w0.z, fmaf(mv.y, w1.z, a2));
                        a3 = fmaf(mv.x, w0.w, fmaf(mv.y, w1.w, a3));
                    }
                }
                const float mk = s_mask[j];
                s_out[(4 * quad + 0) * 96 + j] = a0 * mk;
                s_out[(4 * quad + 1) * 96 + j] = a1 * mk;
                s_out[(4 * quad + 2) * 96 + j] = a2 * mk;
                s_out[(4 * quad + 3) * 96 + j] = a3 * mk;
            }
        }
        __syncthreads();

        for (int t = 0; t < 6; t++) {
            const int idx = tid + t * 256;
            const int c = idx / 96, j = idx - c * 96;
            const size_t gidx = ((size_t)(b * C_ + c0 + c) * H_ + i) * W_ + j;
            outdst[gidx] = basesrc[gidx] + s_out[idx];
        }
        __syncthreads();
    }
}

// ---------------------------------------------------------------------------
// Host launcher
// ---------------------------------------------------------------------------
extern "C" void kernel_launch(void* const* d_in, const int* in_sizes, int n_in,
                              void* d_out, int out_size)
{
    const float *xL, *xR, *catL, *catR;
    const float *bng, *bnb, *bnm, *bnv, *w1, *b1, *w2, *b2, *bqw, *bqb, *bsw, *bsb;
    const int *dL, *dR;

    const bool dict_order = (n_in >= 18) && (in_sizes[4] == B_ * H_ * W_);
    if (dict_order) {
        xL   = (const float*)d_in[0];  xR   = (const float*)d_in[1];
        catL = (const float*)d_in[2];  catR = (const float*)d_in[3];
        dL   = (const int*)  d_in[4];  dR   = (const int*)  d_in[5];
        bng  = (const float*)d_in[6];  bnb  = (const float*)d_in[7];
        bnm  = (const float*)d_in[8];  bnv  = (const float*)d_in[9];
        w1   = (const float*)d_in[10]; b1   = (const float*)d_in[11];
        w2   = (const float*)d_in[12]; b2   = (const float*)d_in[13];
        bqw  = (const float*)d_in[14]; bqb  = (const float*)d_in[15];
        bsw  = (const float*)d_in[16]; bsb  = (const float*)d_in[17];
    } else {
        xL   = (const float*)d_in[0];  xR   = (const float*)d_in[1];
        catL = (const float*)d_in[2];  catR = (const float*)d_in[3];
        bng  = (const float*)d_in[4];  bnb  = (const float*)d_in[5];
        bnm  = (const float*)d_in[6];  bnv  = (const float*)d_in[7];
        w1   = (const float*)d_in[8];  b1   = (const float*)d_in[9];
        w2   = (const float*)d_in[10]; b2   = (const float*)d_in[11];
        bqw  = (const float*)d_in[12]; bqb  = (const float*)d_in[13];
        bsw  = (const float*)d_in[14]; bsb  = (const float*)d_in[15];
        dL   = (const int*)  d_in[16]; dR   = (const int*)  d_in[17];
    }

    float *t1, *t2, *Qb, *Kb;
    cudaGetSymbolAddress((void**)&t1, g_t1);
    cudaGetSymbolAddress((void**)&t2, g_t2);
    cudaGetSymbolAddress((void**)&Qb, g_Q);
    cudaGetSymbolAddress((void**)&Kb, g_K);

    cudaFuncSetAttribute(conv3x3_kernel<1>,
                         cudaFuncAttributeMaxDynamicSharedMemorySize, CONV_SMEM);
    cudaFuncSetAttribute(conv3x3_kernel<2>,
                         cudaFuncAttributeMaxDynamicSharedMemorySize, CONV_SMEM);
    cudaFuncSetAttribute(attention_kernel,
                         cudaFuncAttributeMaxDynamicSharedMemorySize, ATT_SMEM);

    // oc-split: grid (3, 8, 32) = 768 blocks, 3 blocks/SM
    const dim3 cgrid(W_ / TW, H_ / TH, NSB * 8);

    conv3x3_kernel<1><<<cgrid, 256, CONV_SMEM>>>(catL, catR, nullptr, w1, b1,
                                                 bng, bnb, bnm, bnv, t1);
    conv3x3_kernel<2><<<cgrid, 256, CONV_SMEM>>>(catL, catR, t1, w2, b2,
                                                 bng, bnb, bnm, bnv, t2);
    conv1x1_kernel<<<dim3(6, 1, 16), 256>>>(t2, bqw, bqb, bsw, bsb, Qb, Kb);

    float* outL = (float*)d_out;
    float* outR = outL + (size_t)B_ * C_ * HW_;
    attention_kernel<<<dim3(H_, B_, 2), 256, ATT_SMEM>>>(Qb, Kb, xL, xR, dL, dR,
                                                         outL, outR);
}

// round 15
// speedup vs baseline: 1.3635x; 1.0070x over previous
#include <cuda_runtime.h>
#include <cstddef>

// ---------------------------------------------------------------------------
// Problem constants
// ---------------------------------------------------------------------------
constexpr int B_  = 2;
constexpr int C_  = 64;
constexpr int C4_ = 256;
constexpr int H_  = 64;
constexpr int W_  = 96;
constexpr int HW_ = H_ * W_;
constexpr int NSB = 2 * B_;   // side * batch slots

typedef unsigned long long ull;

// Scratch (device globals: no allocations allowed). Layout [side*B+b][C4][HW]
__device__ float g_t1[(size_t)NSB * C4_ * HW_];
__device__ float g_t2[(size_t)NSB * C4_ * HW_];
__device__ float g_Q [(size_t)B_ * C_  * HW_];
__device__ float g_K [(size_t)B_ * C_  * HW_];

// ---------------------------------------------------------------------------
// f32x2 helpers (sm_100+ packed fp32 — exact, two independent IEEE FMAs)
// ---------------------------------------------------------------------------
__device__ __forceinline__ ull pk2(float a, float b) {
    ull r;
    asm("mov.b64 %0, {%1, %2};" : "=l"(r)
        : "r"(__float_as_uint(a)), "r"(__float_as_uint(b)));
    return r;
}
__device__ __forceinline__ void fma2(ull& d, ull a, ull b) {
    asm("fma.rn.f32x2 %0, %1, %2, %0;" : "+l"(d) : "l"(a), "l"(b));
}
__device__ __forceinline__ void unpk2(ull v, float& lo, float& hi) {
    unsigned l, h;
    asm("mov.b64 {%0, %1}, %2;" : "=r"(l), "=r"(h) : "l"(v));
    lo = __uint_as_float(l); hi = __uint_as_float(h);
}

// ---------------------------------------------------------------------------
// Grouped 3x3 conv (groups=4, in=out=256ch), stride 1, pad 1.
// OC-SPLIT: 32 oc per block, 8x32 tile, 768 blocks, 3 blocks/SM.
// REGISTER PREFETCH PIPELINE: loads for icb+1 issue during compute of icb
// (thread-private registers need no sync) -> LDG latency hidden by compute.
// MODE1 applies BN per element at load (boundary-correct: pads stay 0).
// MODE2 epilogue: conv + bias + BN(cat) residual.
// ---------------------------------------------------------------------------
constexpr int TH   = 8;
constexpr int TW   = 32;
constexpr int ICB  = 8;
constexpr int INROW   = TW + 2;   // 34 valid cols
constexpr int INPITCH = 36;       // even pitch -> float2-aligned rows

constexpr int IN_ELEMS  = ICB * 10 * INROW;        // 2720
constexpr int CONV_W2   = 32 * 72;                 // 2304 ull = 18432 B
constexpr int CONV_IN   = ICB * 10 * INPITCH;      // 2880 floats = 11520 B
constexpr int CONV_SMEM = CONV_W2 * 8 + CONV_IN * 4 + 2 * 64 * 4;  // ~30.5 KB

template <int MODE>
__global__ __launch_bounds__(256, 3)
void conv3x3_kernel(const float* __restrict__ catL,
                    const float* __restrict__ catR,
                    const float* __restrict__ tin,
                    const float* __restrict__ wgt,   // (256, 64, 3, 3)
                    const float* __restrict__ bias,  // (256)
                    const float* __restrict__ bn_g,
                    const float* __restrict__ bn_b,
                    const float* __restrict__ bn_m,
                    const float* __restrict__ bn_v,
                    float* __restrict__ out)
{
    extern __shared__ unsigned char csm[];
    ull*   s_w2 = (ull*)csm;                       // [oc*72 + c*9 + tap], oc<32
    float* s_in = (float*)(s_w2 + CONV_W2);        // [c][10][36]
    float* s_sc = s_in + CONV_IN;                  // per-channel-in-group BN
    float* s_sh = s_sc + 64;

    const int tid = threadIdx.x;
    const int bz  = blockIdx.z;        // (((s*2+b)*4+g)*2 + oh)
    const int oh  = bz & 1;
    const int g   = (bz >> 1) & 3;
    const int b   = (bz >> 3) & 1;
    const int s   = bz >> 4;
    const int sb  = s * B_ + b;
    const int y0  = blockIdx.y * TH;
    const int x0  = blockIdx.x * TW;
    const int gbase = g * 64;                      // input-channel group base
    const int obase = g * 64 + oh * 32;            // output-channel base

    const float* cat = s ? catR : catL;

    if (tid < 64) {
        const int ch = gbase + tid;
        const float sc = bn_g[ch] * rsqrtf(bn_v[ch] + 1e-5f);
        s_sc[tid] = sc;
        s_sh[tid] = bn_b[ch] - bn_m[ch] * sc;
    }

    const int og   = tid >> 5;        // 0..7 -> 4-oc group
    const int p    = tid & 31;
    const int rowp = p >> 2;          // 0..7
    const int colp = (p & 3) * 8;     // 0,8,16,24

    ull acc2[4][4];
#pragma unroll
    for (int o = 0; o < 4; o++)
#pragma unroll
        for (int q = 0; q < 4; q++) acc2[o][q] = 0ULL;

    const float* inb = (MODE == 1)
        ? cat + (size_t)(b * C4_ + gbase) * HW_
        : tin + (size_t)(sb * C4_ + gbase) * HW_;

    __syncthreads();  // s_sc/s_sh ready (needed by loadRegs for MODE1)

    float rin[11];
    float rwv[9];

    auto loadRegs = [&](int icb) {
#pragma unroll
        for (int t = 0; t < 11; t++) {
            const int idx = tid + t * 256;
            float v = 0.f;
            if (idx < IN_ELEMS) {
                const int c   = idx / 340;        // 10*34
                const int rem = idx - c * 340;
                const int r   = rem / 34;
                const int cc  = rem - r * 34;
                const int gy  = y0 - 1 + r;
                const int gx  = x0 - 1 + cc;
                if ((unsigned)gy < (unsigned)H_ && (unsigned)gx < (unsigned)W_) {
                    v = inb[(size_t)(icb + c) * HW_ + gy * W_ + gx];
                    if (MODE == 1)
                        v = v * s_sc[icb + c] + s_sh[icb + c];
                }
            }
            rin[t] = v;
        }
#pragma unroll
        for (int t = 0; t < 9; t++) {
            const int idx = tid + t * 256;        // < 2304 always
            const int oc  = idx / 72;
            const int r   = idx - oc * 72;        // c*9 + tap
            const int c   = r / 9;
            const int tap = r - c * 9;
            rwv[t] = wgt[(size_t)(obase + oc) * 576 + (icb + c) * 9 + tap];
        }
    };

    auto storeRegs = [&]() {
#pragma unroll
        for (int t = 0; t < 11; t++) {
            const int idx = tid + t * 256;
            if (idx < IN_ELEMS) {
                const int c   = idx / 340;
                const int rem = idx - c * 340;
                const int r   = rem / 34;
                const int cc  = rem - r * 34;
                s_in[(c * 10 + r) * INPITCH + cc] = rin[t];
            }
        }
#pragma unroll
        for (int t = 0; t < 9; t++)
            s_w2[tid + t * 256] = pk2(rwv[t], rwv[t]);
    };

    loadRegs(0);

#pragma unroll 1
    for (int step = 0; step < 8; step++) {
        if (step) __syncthreads();    // previous compute done reading smem
        storeRegs();
        __syncthreads();              // staged data visible
        if (step < 7) loadRegs((step + 1) * ICB);   // LDGs in flight under compute

        // -------- compute --------
#pragma unroll 2
        for (int c = 0; c < ICB; c++) {
            float xv[3][10];
#pragma unroll
            for (int kh = 0; kh < 3; kh++) {
                const float* rp = &s_in[(c * 10 + rowp + kh) * INPITCH + colp];
#pragma unroll
                for (int t5 = 0; t5 < 5; t5++) {
                    const float2 v = ((const float2*)rp)[t5];
                    xv[kh][2 * t5]     = v.x;
                    xv[kh][2 * t5 + 1] = v.y;
                }
            }
            const ull* wbase = &s_w2[(og * 4) * 72 + c * 9];
#pragma unroll
            for (int kh = 0; kh < 3; kh++) {
#pragma unroll
                for (int t = 0; t < 3; t++) {
                    const int tap = kh * 3 + t;
                    const ull xp0 = pk2(xv[kh][t],     xv[kh][t + 1]);
                    const ull xp1 = pk2(xv[kh][t + 2], xv[kh][t + 3]);
                    const ull xp2 = pk2(xv[kh][t + 4], xv[kh][t + 5]);
                    const ull xp3 = pk2(xv[kh][t + 6], xv[kh][t + 7]);
#pragma unroll
                    for (int o = 0; o < 4; o++) {
                        const ull w = wbase[o * 72 + tap];   // LDS.64 broadcast
                        fma2(acc2[o][0], w, xp0);
                        fma2(acc2[o][1], w, xp1);
                        fma2(acc2[o][2], w, xp2);
                        fma2(acc2[o][3], w, xp3);
                    }
                }
            }
        }
    }

    // epilogue
    const float* catb = cat + (size_t)(b * C4_ + obase) * HW_;
    float*       outb = out + (size_t)(sb * C4_ + obase) * HW_;
    const int y = y0 + rowp;
#pragma unroll
    for (int o = 0; o < 4; o++) {
        const int oc  = og * 4 + o;            // 0..31 within this half
        const int cig = oh * 32 + oc;          // channel-in-group for BN
        const float bv = bias[obase + oc];
#pragma unroll
        for (int pq = 0; pq < 4; pq++) {
            float v0, v1;
            unpk2(acc2[o][pq], v0, v1);
#pragma unroll
            for (int half = 0; half < 2; half++) {
                const int x = x0 + colp + 2 * pq + half;
                float v = (half ? v1 : v0) + bv;
                if (MODE == 1) {
                    v = (v > 0.f) ? v : 0.1f * v;         // LeakyReLU(0.1)
                } else {
                    const float cv = catb[(size_t)oc * HW_ + y * W_ + x];
                    v += cv * s_sc[cig] + s_sh[cig];
                }
                outb[(size_t)oc * HW_ + y * W_ + x] = v;
            }
        }
    }
}

// ---------------------------------------------------------------------------
// Grouped 1x1 conv (FROZEN).
// ---------------------------------------------------------------------------
__global__ __launch_bounds__(256)
void conv1x1_kernel(const float* __restrict__ in,    // t2 [sb][256][HW]
                    const float* __restrict__ bqw, const float* __restrict__ bqb,
                    const float* __restrict__ bsw, const float* __restrict__ bsb,
                    float* __restrict__ Qb, float* __restrict__ Kb)
{
    __shared__ ulonglong2 s_wt2[64 * 8];   // [ic][ocpair], 8KB

    const int tid = threadIdx.x;
    const int bz  = blockIdx.z;
    const int s   = bz >> 3;
    const int b   = (bz >> 2) & 1;
    const int g   = bz & 3;

    const float* wsel = s ? bsw : bqw;
    const float* bsel = s ? bsb : bqb;

    for (int idx = tid; idx < 512; idx += 256) {
        const int ic = idx >> 3;
        const int op = idx & 7;
        const float wa = wsel[(g * 16 + 2 * op)     * 64 + ic];
        const float wb = wsel[(g * 16 + 2 * op + 1) * 64 + ic];
        s_wt2[idx] = make_ulonglong2(pk2(wa, wa), pk2(wb, wb));
    }
    __syncthreads();

    const int px0 = blockIdx.x * 1024 + tid * 4;
    const float* ip = in + (size_t)((s * B_ + b) * C4_ + g * 64) * HW_ + px0;

    ull acc[16][2];
#pragma unroll
    for (int o = 0; o < 16; o++) {
        const float bv = bsel[g * 16 + o];
        acc[o][0] = pk2(bv, bv);
        acc[o][1] = pk2(bv, bv);
    }

    for (int ic = 0; ic < 64; ic++) {
        const float4 v = *(const float4*)&ip[(size_t)ic * HW_];
        const ull v01 = pk2(v.x, v.y);
        const ull v23 = pk2(v.z, v.w);
        const ulonglong2* wp = &s_wt2[ic * 8];
#pragma unroll
        for (int op = 0; op < 8; op++) {
            const ulonglong2 w = wp[op];          // LDS.128 broadcast
            fma2(acc[2 * op][0],     w.x, v01);
            fma2(acc[2 * op][1],     w.x, v23);
            fma2(acc[2 * op + 1][0], w.y, v01);
            fma2(acc[2 * op + 1][1], w.y, v23);
        }
    }

    float* op_ = (s ? Kb : Qb) + (size_t)(b * C_ + g * 16) * HW_ + px0;
#pragma unroll
    for (int o = 0; o < 16; o++) {
        float4 r;
        unpk2(acc[o][0], r.x, r.y);
        unpk2(acc[o][1], r.z, r.w);
        *(float4*)&op_[(size_t)o * HW_] = r;
    }
}

// ---------------------------------------------------------------------------
// Attention kernel v3 (R11 measured-best — FROZEN). float4 channel-quads,
// register-resident logit accumulators. Grid (H, B, dir).
// ---------------------------------------------------------------------------
constexpr int ROWP4  = 105;             // row pitch in float4 units
constexpr int CSTR4  = 8 * ROWP4 + 5;   // 845, quad stride (float4)
constexpr int NQUAD  = 4;               // quads per chunk (16 channels)
constexpr int WIN_F4 = NQUAD * CSTR4;   // 3380 float4 = 54080 B
constexpr int CEN_F4 = NQUAD * 96;      // 384 float4 = 6144 B
constexpr int MPITCH = 66;
constexpr int M_F    = 96 * MPITCH;     // 6336 floats = 25344 B
constexpr int OUT_F  = 16 * 96;         // 1536 floats = 6144 B
constexpr int ATT_SMEM = WIN_F4 * 16 + CEN_F4 * 16 + M_F * 4 + OUT_F * 4 + 5 * 96 * 4;

__global__ __launch_bounds__(256, 2)
void attention_kernel(const float* __restrict__ Qf, const float* __restrict__ Kf,
                      const float* __restrict__ xL, const float* __restrict__ xR,
                      const int* __restrict__ dL, const int* __restrict__ dR,
                      float* __restrict__ outL, float* __restrict__ outR)
{
    extern __shared__ float smem[];
    float4* s_win4 = (float4*)smem;                 // WIN_F4
    float4* s_cen4 = s_win4 + WIN_F4;               // CEN_F4
    float*  s_M    = (float*)(s_cen4 + CEN_F4);     // M_F
    float*  s_out  = s_M + M_F;                     // OUT_F
    int*    s_cc   = (int*)(s_out + OUT_F);         // 96  logits centers
    int*    s_cv   = s_cc + 96;                     // 96  value centers (= cr)
    int*    s_sval = s_cv + 96;                     // 96  softmax validity
    int*    s_vval = s_sval + 96;                   // 96  value validity (= vR)
    float*  s_mask = (float*)(s_vval + 96);         // 96  output mask

    const int i   = blockIdx.x;
    const int b   = blockIdx.y;
    const int z   = blockIdx.z;                     // 0=r2l, 1=l2r
    const int tid = threadIdx.x;

    if (tid < 96) {
        const int j  = tid;
        const int dl = dL[(b * H_ + i) * W_ + j];
        const int dr = dR[(b * H_ + i) * W_ + j];
        const int cr = max(j - dl, 0);
        const int cl = min(j + dr, W_ - 1);
        const int rowok = (i + 4) < H_;
        const int vR = (rowok && cr < W_ - 4) ? 1 : 0;
        const int vL = (rowok && cl < W_ - 4) ? 1 : 0;
        s_cc[j]   = z ? cl : cr;
        s_cv[j]   = cr;                             // value coords always r2l
        s_sval[j] = z ? vL : vR;
        s_vval[j] = vR;                             // value validity always vR
        s_mask[j] = z ? ((j + dr <= W_ - 1) ? 1.f : 0.f)
                      : ((j - dl >= 0)      ? 1.f : 0.f);
    }
    const float4 zero4 = make_float4(0.f, 0.f, 0.f, 0.f);
    for (int idx = tid; idx < WIN_F4; idx += 256) s_win4[idx] = zero4;
    __syncthreads();

    const float* winsrc = z ? Qf : Kf;
    const float* censrc = z ? Kf : Qf;
    const int kbit  = tid & 1;
    const int koff  = kbit * 32;
    const int aoff4 = kbit * 4 * ROWP4;
    const int jlog  = tid >> 1;
    const int cc    = (tid < 192) ? s_cc[jlog] : 0;

    // ---- logits: 4 chunks of 4 channel quads; acc stays in registers ----
    float acc[32];
#pragma unroll
    for (int kk = 0; kk < 32; kk++) acc[kk] = 0.f;

    for (int cb = 0; cb < 4; cb++) {
        const int c0 = cb * 16;
        const float* wsb = winsrc + (size_t)(b * C_ + c0) * HW_;
        for (int idx = tid; idx < NQUAD * 768; idx += 256) {
            const int q   = idx / 768;
            const int rem = idx - q * 768;           // a*96 + col
            const int a   = rem / 96;
            const int col = rem - a * 96;
            const int gy  = i - 4 + a;
            float4 v = zero4;
            if ((unsigned)gy < (unsigned)H_) {
                const float* p = wsb + (size_t)(4 * q) * HW_ + gy * W_ + col;
                v.x = p[0]; v.y = p[HW_]; v.z = p[2 * HW_]; v.w = p[3 * HW_];
            }
            s_win4[q * CSTR4 + a * ROWP4 + 4 + col] = v;
        }
        const float* csb = censrc + (size_t)(b * C_ + c0) * HW_ + (size_t)i * W_;
        for (int idx = tid; idx < NQUAD * 96; idx += 256) {
            const int q = idx / 96, j = idx - q * 96;
            const float* p = csb + (size_t)(4 * q) * HW_ + j;
            s_cen4[idx] = make_float4(p[0], p[HW_], p[2 * HW_], p[3 * HW_]);
        }
        __syncthreads();

        if (tid < 192) {
#pragma unroll
            for (int q = 0; q < NQUAD; q++) {
                const float4 cen = s_cen4[q * 96 + jlog];
                const float4* wb = s_win4 + q * CSTR4 + cc + aoff4;
#pragma unroll
                for (int kk = 0; kk < 32; kk++) {
                    const float4 w = wb[(kk >> 3) * ROWP4 + (kk & 7)];
                    acc[kk] = fmaf(cen.x, w.x,
                              fmaf(cen.y, w.y,
                              fmaf(cen.z, w.z,
                              fmaf(cen.w, w.w, acc[kk]))));
                }
            }
        }
        __syncthreads();
    }

    if (tid < 192) {
        float* Mrow = s_M + jlog * MPITCH + koff;
#pragma unroll
        for (int kk = 0; kk < 32; kk++) Mrow[kk] = acc[kk];
    }
    __syncthreads();

    // ---- softmax ----
    if (tid < 96) {
        float* row = s_M + tid * MPITCH;
        if (!s_sval[tid]) {
#pragma unroll
            for (int k = 0; k < 64; k++) row[k] = 1.f / 64.f;
        } else {
            float mx = row[0];
#pragma unroll
            for (int k = 1; k < 64; k++) mx = fmaxf(mx, row[k]);
            float ssum = 0.f;
#pragma unroll
            for (int k = 0; k < 64; k++) {
                const float e = __expf(row[k] - mx);
                row[k] = e; ssum += e;
            }
            const float inv = 1.f / ssum;
#pragma unroll
            for (int k = 0; k < 64; k++) row[k] *= inv;
        }
    }
    __syncthreads();

    // ---- value pass: 4 chunks of 4 channel quads ----
    const float* valsrc  = z ? xL : xR;
    const float* basesrc = z ? xR : xL;
    float*       outdst  = z ? outR : outL;
    const int quad = tid & 3;
    const int jg   = tid >> 2;           // 0..63

    for (int cb = 0; cb < 4; cb++) {
        const int c0 = cb * 16;
        const float* vsb = valsrc + (size_t)(b * C_ + c0) * HW_;
        for (int idx = tid; idx < NQUAD * 768; idx += 256) {
            const int q   = idx / 768;
            const int rem = idx - q * 768;
            const int a   = rem / 96;
            const int col = rem - a * 96;
            const int gy  = i - 4 + a;
            float4 v = zero4;
            if ((unsigned)gy < (unsigned)H_) {
                const float* p = vsb + (size_t)(4 * q) * HW_ + gy * W_ + col;
                v.x = p[0]; v.y = p[HW_]; v.z = p[2 * HW_]; v.w = p[3 * HW_];
            }
            s_win4[q * CSTR4 + a * ROWP4 + 4 + col] = v;
        }
        __syncthreads();

#pragma unroll
        for (int m = 0; m < 2; m++) {
            const int j = jg + 64 * m;
            if (j < 96) {
                float a0 = 0.f, a1 = 0.f, a2 = 0.f, a3 = 0.f;
                if (s_vval[j]) {
                    const float4* wb   = s_win4 + quad * CSTR4 + s_cv[j];
                    const float*  Mrow = s_M + j * MPITCH;
#pragma unroll
                    for (int kp = 0; kp < 32; kp++) {
                        const float2 mv = *(const float2*)(Mrow + 2 * kp);
                        const int k0 = 2 * kp, k1 = 2 * kp + 1;
                        const float4 w0 = wb[(k0 >> 3) * ROWP4 + (k0 & 7)];
                        const float4 w1 = wb[(k1 >> 3) * ROWP4 + (k1 & 7)];
                        a0 = fmaf(mv.x, w0.x, fmaf(mv.y, w1.x, a0));
                        a1 = fmaf(mv.x, w0.y, fmaf(mv.y, w1.y, a1));
                        a2 = fmaf(mv.x, w0.z, fmaf(mv.y, w1.z, a2));
                        a3 = fmaf(mv.x, w0.w, fmaf(mv.y, w1.w, a3));
                    }
                }
                const float mk = s_mask[j];
                s_out[(4 * quad + 0) * 96 + j] = a0 * mk;
                s_out[(4 * quad + 1) * 96 + j] = a1 * mk;
                s_out[(4 * quad + 2) * 96 + j] = a2 * mk;
                s_out[(4 * quad + 3) * 96 + j] = a3 * mk;
            }
        }
        __syncthreads();

        for (int t = 0; t < 6; t++) {
            const int idx = tid + t * 256;
            const int c = idx / 96, j = idx - c * 96;
            const size_t gidx = ((size_t)(b * C_ + c0 + c) * H_ + i) * W_ + j;
            outdst[gidx] = basesrc[gidx] + s_out[idx];
        }
        __syncthreads();
    }
}

// ---------------------------------------------------------------------------
// Host launcher
// ---------------------------------------------------------------------------
extern "C" void kernel_launch(void* const* d_in, const int* in_sizes, int n_in,
                              void* d_out, int out_size)
{
    const float *xL, *xR, *catL, *catR;
    const float *bng, *bnb, *bnm, *bnv, *w1, *b1, *w2, *b2, *bqw, *bqb, *bsw, *bsb;
    const int *dL, *dR;

    const bool dict_order = (n_in >= 18) && (in_sizes[4] == B_ * H_ * W_);
    if (dict_order) {
        xL   = (const float*)d_in[0];  xR   = (const float*)d_in[1];
        catL = (const float*)d_in[2];  catR = (const float*)d_in[3];
        dL   = (const int*)  d_in[4];  dR   = (const int*)  d_in[5];
        bng  = (const float*)d_in[6];  bnb  = (const float*)d_in[7];
        bnm  = (const float*)d_in[8];  bnv  = (const float*)d_in[9];
        w1   = (const float*)d_in[10]; b1   = (const float*)d_in[11];
        w2   = (const float*)d_in[12]; b2   = (const float*)d_in[13];
        bqw  = (const float*)d_in[14]; bqb  = (const float*)d_in[15];
        bsw  = (const float*)d_in[16]; bsb  = (const float*)d_in[17];
    } else {
        xL   = (const float*)d_in[0];  xR   = (const float*)d_in[1];
        catL = (const float*)d_in[2];  catR = (const float*)d_in[3];
        bng  = (const float*)d_in[4];  bnb  = (const float*)d_in[5];
        bnm  = (const float*)d_in[6];  bnv  = (const float*)d_in[7];
        w1   = (const float*)d_in[8];  b1   = (const float*)d_in[9];
        w2   = (const float*)d_in[10]; b2   = (const float*)d_in[11];
        bqw  = (const float*)d_in[12]; bqb  = (const float*)d_in[13];
        bsw  = (const float*)d_in[14]; bsb  = (const float*)d_in[15];
        dL   = (const int*)  d_in[16]; dR   = (const int*)  d_in[17];
    }

    float *t1, *t2, *Qb, *Kb;
    cudaGetSymbolAddress((void**)&t1, g_t1);
    cudaGetSymbolAddress((void**)&t2, g_t2);
    cudaGetSymbolAddress((void**)&Qb, g_Q);
    cudaGetSymbolAddress((void**)&Kb, g_K);

    cudaFuncSetAttribute(conv3x3_kernel<1>,
                         cudaFuncAttributeMaxDynamicSharedMemorySize, CONV_SMEM);
    cudaFuncSetAttribute(conv3x3_kernel<2>,
                         cudaFuncAttributeMaxDynamicSharedMemorySize, CONV_SMEM);
    cudaFuncSetAttribute(attention_kernel,
                         cudaFuncAttributeMaxDynamicSharedMemorySize, ATT_SMEM);

    // oc-split: grid (3, 8, 32) = 768 blocks, 3 blocks/SM
    const dim3 cgrid(W_ / TW, H_ / TH, NSB * 8);

    conv3x3_kernel<1><<<cgrid, 256, CONV_SMEM>>>(catL, catR, nullptr, w1, b1,
                                                 bng, bnb, bnm, bnv, t1);
    conv3x3_kernel<2><<<cgrid, 256, CONV_SMEM>>>(catL, catR, t1, w2, b2,
                                                 bng, bnb, bnm, bnv, t2);
    conv1x1_kernel<<<dim3(6, 1, 16), 256>>>(t2, bqw, bqb, bsw, bsb, Qb, Kb);

    float* outL = (float*)d_out;
    float* outR = outL + (size_t)B_ * C_ * HW_;
    attention_kernel<<<dim3(H_, B_, 2), 256, ATT_SMEM>>>(Qb, Kb, xL, xR, dL, dR,
                                                         outL, outR);
}